// round 5
// baseline (speedup 1.0000x reference)
#include <cuda_runtime.h>
#include <cuda_bf16.h>

#define N_NODES 20000
#define N_EDGES 200000
#define IN_DIM  500
#define HID     256
#define OUT_DIM 16
#define MHD     64

typedef unsigned long long ull;

// ---- packed fp32x2 helpers (sm_103a FFMA2 — only reachable via PTX) ----
__device__ __forceinline__ ull fpack2(float lo, float hi) {
    ull r; asm("mov.b64 %0, {%1, %2};" : "=l"(r) : "f"(lo), "f"(hi)); return r;
}
__device__ __forceinline__ void ffma2(ull &d, ull a, ull b) {
    asm("fma.rn.f32x2 %0, %1, %2, %0;" : "+l"(d) : "l"(a), "l"(b));
}
__device__ __forceinline__ float2 funpack2(ull v) {
    float2 r; asm("mov.b64 {%0, %1}, %2;" : "=f"(r.x), "=f"(r.y) : "l"(v)); return r;
}

// ---------------- device scratch (static, no allocations) ----------------
struct ZS {                     // zeroed by ONE memset each launch
    int   cnt[N_NODES];
    float D[N_NODES * 16];      // per-node sum of P (as src) + S (as dst)
};
__device__ ZS    g_zs;
__device__ float g_h  [N_NODES * HID];     // h, then xb (updated in place)
__device__ float g_h1 [N_NODES * MHD];     // MLP intermediates
__device__ float g_AB [N_NODES * 2 * MHD]; // [N][128]: A | B
__device__ float g_Wc [2 * MHD * MHD];     // combined (Wab @ Win2) -> [128][64]
__device__ float g_bc [2 * MHD];           // combined bias Wab @ bin2
__device__ ull   g_Q  [(size_t)N_EDGES * 32]; // per edge: 16 ull {q,q} for Q, 16 for Q^T
__device__ float g_H  [N_NODES * HID];     // diffusion operand H per layer
__device__ int   g_off[N_NODES + 1];
__device__ int   g_cur[N_NODES];
__device__ int   g_incid[2 * N_EDGES];     // (e<<1)|role ; role 0=src,1=dst

// ---------------- SGEMM: C = act(A[M,K] @ W[N,K]^T + b), FFMA2 core ------
template<bool RELU>
__global__ __launch_bounds__(256)
void sgemm128(const float* __restrict__ A, const float* __restrict__ W,
              const float* __restrict__ bias, float* __restrict__ C,
              int M, int N, int K)
{
    __shared__ float As[16][132];
    __shared__ float Ws[16][68];

    int tid = threadIdx.x;
    int tx = tid & 15, ty = tid >> 4;
    int row0 = blockIdx.y * 128, col0 = blockIdx.x * 64;

    int arow = tid >> 1;
    int akb  = (tid & 1) * 8;
    int wcol = tid & 63;
    int wkb  = (tid >> 6) * 4;

    int gr = row0 + arow;
    int gc = col0 + wcol;
    const float* Arow = A + (size_t)(gr < M ? gr : 0) * K;
    const float* Wrow = W + (size_t)(gc < N ? gc : 0) * K;
    bool rok = gr < M;
    bool cok = gc < N;

    ull acc2[4][4] = {};           // [m-pair][n], lo = even row
    float ra[8], rw[4];

    #pragma unroll
    for (int u = 0; u < 8; u++) {
        int k = akb + u;
        ra[u] = (rok && k < K) ? Arow[k] : 0.f;
    }
    #pragma unroll
    for (int u = 0; u < 4; u++) {
        int k = wkb + u;
        rw[u] = (cok && k < K) ? Wrow[k] : 0.f;
    }

    for (int k0 = 0; k0 < K; k0 += 16) {
        #pragma unroll
        for (int u = 0; u < 8; u++) As[akb + u][arow] = ra[u];
        #pragma unroll
        for (int u = 0; u < 4; u++) Ws[wkb + u][wcol] = rw[u];
        __syncthreads();

        int kn = k0 + 16;
        if (kn < K) {
            #pragma unroll
            for (int u = 0; u < 8; u++) {
                int k = kn + akb + u;
                ra[u] = (rok && k < K) ? Arow[k] : 0.f;
            }
            #pragma unroll
            for (int u = 0; u < 4; u++) {
                int k = kn + wkb + u;
                rw[u] = (cok && k < K) ? Wrow[k] : 0.f;
            }
        }

        #pragma unroll
        for (int kk = 0; kk < 16; kk++) {
            ulonglong2 av0 = *(const ulonglong2*)&As[kk][ty * 8];
            ulonglong2 av1 = *(const ulonglong2*)&As[kk][ty * 8 + 4];
            float4 b0 = *(const float4*)&Ws[kk][tx * 4];
            ull am[4] = {av0.x, av0.y, av1.x, av1.y};
            ull b2[4] = {fpack2(b0.x, b0.x), fpack2(b0.y, b0.y),
                         fpack2(b0.z, b0.z), fpack2(b0.w, b0.w)};
            #pragma unroll
            for (int i = 0; i < 4; i++)
                #pragma unroll
                for (int j = 0; j < 4; j++)
                    ffma2(acc2[i][j], am[i], b2[j]);
        }
        __syncthreads();
    }

    #pragma unroll
    for (int i = 0; i < 4; i++) {
        int r0 = row0 + ty * 8 + 2 * i;
        #pragma unroll
        for (int j = 0; j < 4; j++) {
            int c = col0 + tx * 4 + j;
            if (c >= N) continue;
            float2 v = funpack2(acc2[i][j]);
            float b = bias ? bias[c] : 0.f;
            float v0 = v.x + b, v1 = v.y + b;
            if (RELU) { v0 = fmaxf(v0, 0.f); v1 = fmaxf(v1, 0.f); }
            if (r0 < M)     C[(size_t)r0 * N + c] = v0;
            if (r0 + 1 < M) C[(size_t)(r0 + 1) * N + c] = v1;
        }
    }
}

// ---------------- CSR build ----------------
__global__ void count_kernel(const int* __restrict__ ei) {
    int e = blockIdx.x * 256 + threadIdx.x;
    if (e < N_EDGES) {
        atomicAdd(&g_zs.cnt[ei[e]], 1);
        atomicAdd(&g_zs.cnt[ei[N_EDGES + e]], 1);
    }
}

__global__ void scan_kernel() {
    const int CH = (N_NODES + 1023) / 1024;  // 20
    __shared__ int ssum[1024];
    int tid = threadIdx.x;
    int begin = tid * CH;
    int endi = begin + CH; if (endi > N_NODES) endi = N_NODES;
    int s = 0;
    for (int i = begin; i < endi; i++) s += g_zs.cnt[i];
    ssum[tid] = s;
    __syncthreads();
    for (int off = 1; off < 1024; off <<= 1) {
        int v = 0;
        if (tid >= off) v = ssum[tid - off];
        __syncthreads();
        ssum[tid] += v;
        __syncthreads();
    }
    int run = ssum[tid] - s;
    for (int i = begin; i < endi; i++) {
        g_off[i] = run;
        g_cur[i] = run;
        run += g_zs.cnt[i];
    }
    if (tid == 1023) g_off[N_NODES] = ssum[1023];
}

__global__ void fill_kernel(const int* __restrict__ ei) {
    int e = blockIdx.x * 256 + threadIdx.x;
    if (e < N_EDGES) {
        int s = ei[e], d = ei[N_EDGES + e];
        int p = atomicAdd(&g_cur[s], 1);
        g_incid[p] = (e << 1);
        int p2 = atomicAdd(&g_cur[d], 1);
        g_incid[p2] = (e << 1) | 1;
    }
}

// ---------------- combined weights: Wc = Wab @ Win2, bc = Wab @ bin2 -----
__global__ __launch_bounds__(256)
void wc_kernel(const float* __restrict__ Wm1,
               const float* __restrict__ Win2,
               const float* __restrict__ bin2)
{
    __shared__ float part[256];
    __shared__ float bpart[64];
    int i = blockIdx.x;                  // 0..127
    const float* wrow = (i < 64) ? &Wm1[i * 512] : &Wm1[(i - 64) * 512 + 256];
    int t = threadIdx.x;
    int mh = t & 63, kq = t >> 6;
    float s = 0.f;
    #pragma unroll 16
    for (int k = kq * 64; k < kq * 64 + 64; k++)
        s += wrow[k] * Win2[k * 64 + mh];
    part[t] = s;
    if (kq == 0) {
        float b = 0.f;
        #pragma unroll
        for (int k = mh * 4; k < mh * 4 + 4; k++) b += wrow[k] * bin2[k];
        bpart[mh] = b;
    }
    __syncthreads();
    if (kq == 0)
        g_Wc[i * 64 + mh] = part[mh] + part[64 + mh] + part[128 + mh] + part[192 + mh];
    if (t == 0) {
        float bb = 0.f;
        #pragma unroll
        for (int k = 0; k < 64; k++) bb += bpart[k];
        g_bc[i] = bb;
    }
}

// ---------------- per-edge: Q & Q^T stored pre-packed; P,S atomics into D
__global__ __launch_bounds__(256)
void edge_kernel(const int* __restrict__ ei, const float* __restrict__ Wm2,
                 const float* __restrict__ bm1, const float* __restrict__ bm2)
{
    __shared__ float W4s[1024];      // Wm2 repacked: [(k>>2)][o][k&3]
    __shared__ float bm2s[16];
    __shared__ float sbuf[8 * 160];  // per warp: t1[64] t2[64] fsft[32]
    int tid = threadIdx.x;
    for (int idx = tid; idx < 1024; idx += 256) {
        int o = idx >> 6, k = idx & 63;
        W4s[((k >> 2) << 6) + (o << 2) + (k & 3)] = Wm2[idx];
    }
    if (tid < 16) bm2s[tid] = bm2[tid];
    __syncthreads();

    int warp = tid >> 5, lane = tid & 31;
    int e = blockIdx.x * 8 + warp;   // grid 25000, exact
    float* sw = &sbuf[warp * 160];

    int s = ei[e], d = ei[N_EDGES + e];
    int k0 = lane * 2;
    float2 As = *(const float2*)&g_AB[s * 128 + k0];
    float2 Bd = *(const float2*)&g_AB[d * 128 + 64 + k0];
    float2 Ad = *(const float2*)&g_AB[d * 128 + k0];
    float2 Bs = *(const float2*)&g_AB[s * 128 + 64 + k0];
    float2 b1 = *(const float2*)&bm1[k0];
    sw[k0]          = fmaxf(As.x + Bd.x + b1.x, 0.f);
    sw[k0 + 1]      = fmaxf(As.y + Bd.y + b1.y, 0.f);
    sw[64 + k0]     = fmaxf(Ad.x + Bs.x + b1.x, 0.f);
    sw[64 + k0 + 1] = fmaxf(Ad.y + Bs.y + b1.y, 0.f);
    __syncwarp();

    // lanes 0-15 -> fs[o] from t1; lanes 16-31 -> ft[o] from t2
    int o = lane & 15;
    const float* tv = sw + ((lane >> 4) << 6);
    ull acc2 = 0;
    #pragma unroll
    for (int kc = 0; kc < 16; kc++) {
        ulonglong2 t2v = *(const ulonglong2*)&tv[kc * 4];
        ulonglong2 w2v = *(const ulonglong2*)&W4s[kc * 64 + o * 4];
        ffma2(acc2, t2v.x, w2v.x);
        ffma2(acc2, t2v.y, w2v.y);
    }
    float2 af = funpack2(acc2);
    sw[128 + lane] = af.x + af.y + bm2s[o];
    __syncwarp();

    if (lane < 16) {
        int i = lane >> 2, j = lane & 3;
        float p = 0.f, q = 0.f, ss = 0.f;
        #pragma unroll
        for (int m = 0; m < 4; m++) {
            float fsi = sw[128 + m * 4 + i], fsj = sw[128 + m * 4 + j];
            float fti = sw[144 + m * 4 + i], ftj = sw[144 + m * 4 + j];
            p  += fsi * fsj;   // P = Fs^T Fs
            q  += fsi * ftj;   // Q = Fs^T Ft
            ss += fti * ftj;   // S = Ft^T Ft
        }
        ull qd = fpack2(q, q);
        g_Q[(size_t)e * 32 + lane] = qd;                                   // Q
        g_Q[(size_t)e * 32 + 16 + ((lane & 3) << 2) + (lane >> 2)] = qd;   // Q^T
        atomicAdd(&g_zs.D[s * 16 + lane], p);
        atomicAdd(&g_zs.D[d * 16 + lane], ss);
    }
}

// ---------------- per-node H = (Wd1^T @ xb) @ Wd2^T ----------------
__global__ __launch_bounds__(256)
void hcomp_kernel(const float* __restrict__ Wd1, const float* __restrict__ Wd2,
                  int layer)
{
    __shared__ float w2t[64][66];
    __shared__ float h1s[8][4][64];
    int tid = threadIdx.x;
    for (int idx = tid; idx < 4096; idx += 256) {
        int g = idx >> 6, f = idx & 63;
        w2t[f][g] = Wd2[layer * 4096 + idx];
    }
    float wd1[16];
    #pragma unroll
    for (int i = 0; i < 16; i++) wd1[i] = __ldg(&Wd1[layer * 16 + i]);

    int warp = tid >> 5, lane = tid & 31;
    int n = blockIdx.x * 8 + warp;   // grid 2500, exact
    int c0 = lane * 2;
    float2 xv[4];
    #pragma unroll
    for (int j = 0; j < 4; j++)
        xv[j] = *(const float2*)&g_h[n * 256 + j * 64 + c0];
    #pragma unroll
    for (int i = 0; i < 4; i++) {
        h1s[warp][i][c0]     = wd1[i] * xv[0].x + wd1[4 + i] * xv[1].x +
                               wd1[8 + i] * xv[2].x + wd1[12 + i] * xv[3].x;
        h1s[warp][i][c0 + 1] = wd1[i] * xv[0].y + wd1[4 + i] * xv[1].y +
                               wd1[8 + i] * xv[2].y + wd1[12 + i] * xv[3].y;
    }
    __syncthreads();

    ull acc2[4] = {};
    #pragma unroll
    for (int f = 0; f < 64; f++) {
        ull w2v = *(const ull*)&w2t[f][c0];
        #pragma unroll
        for (int k = 0; k < 4; k++) {
            float hv = h1s[warp][k][f];
            ffma2(acc2[k], fpack2(hv, hv), w2v);
        }
    }
    #pragma unroll
    for (int k = 0; k < 4; k++) {
        float2 v = funpack2(acc2[k]);
        *(float2*)&g_H[n * 256 + k * 64 + c0] = v;
    }
}

// ---------------- gather: acc += Qeff @ H[other] (subtracted at the end)
__device__ __forceinline__ void proc_inc(int idx, const int* __restrict__ ei,
                                         int c0, ull acc2[4])
{
    int v = __ldg(&g_incid[idx]);
    int e = v >> 1, role = v & 1;
    int other = __ldg(&ei[role ? e : (N_EDGES + e)]);
    const ull* qp = &g_Q[(size_t)e * 32 + (role << 4)];   // Q or Q^T, pre-packed {q,q}
    const ull* hb = (const ull*)&g_H[(size_t)other * 256 + c0];
    ull h0 = hb[0], h1 = hb[32], h2 = hb[64], h3 = hb[96];

    #pragma unroll
    for (int i = 0; i < 4; i++) {
        ulonglong2 qa = *(const ulonglong2*)&qp[i * 4];
        ulonglong2 qb = *(const ulonglong2*)&qp[i * 4 + 2];
        ffma2(acc2[i], qa.x, h0);
        ffma2(acc2[i], qa.y, h1);
        ffma2(acc2[i], qb.x, h2);
        ffma2(acc2[i], qb.y, h3);
    }
}

__global__ __launch_bounds__(256)
void gather_kernel(const int* __restrict__ ei)
{
    __shared__ ull red2[4][128];
    int warp = threadIdx.x >> 5, lane = threadIdx.x & 31;
    int slot = warp >> 1, w2 = warp & 1;
    int n = blockIdx.x * 4 + slot;   // grid 5000, exact
    int beg = g_off[n], endi = g_off[n + 1];
    int cnt = endi - beg;
    int mid = beg + ((cnt + 1) >> 1);
    int lo = w2 ? mid : beg;
    int hi = w2 ? endi : mid;
    int c0 = lane * 2;

    ull acc2[4] = {};

    int idx = lo;
    for (; idx + 1 < hi; idx += 2) {
        proc_inc(idx,     ei, c0, acc2);
        proc_inc(idx + 1, ei, c0, acc2);
    }
    if (idx < hi) proc_inc(idx, ei, c0, acc2);

    if (w2) {
        #pragma unroll
        for (int k = 0; k < 4; k++) red2[slot][k * 32 + lane] = acc2[k];
    }
    __syncthreads();
    if (!w2) {
        const float4* Dp = (const float4*)&g_zs.D[n * 16];
        float4 Dk[4] = {Dp[0], Dp[1], Dp[2], Dp[3]};
        const ull* hnb = (const ull*)&g_H[(size_t)n * 256 + c0];
        ull hn0 = hnb[0], hn1 = hnb[32], hn2 = hnb[64], hn3 = hnb[96];
        #pragma unroll
        for (int k = 0; k < 4; k++) {
            ull dacc = 0;
            ffma2(dacc, fpack2(Dk[k].x, Dk[k].x), hn0);
            ffma2(dacc, fpack2(Dk[k].y, Dk[k].y), hn1);
            ffma2(dacc, fpack2(Dk[k].z, Dk[k].z), hn2);
            ffma2(dacc, fpack2(Dk[k].w, Dk[k].w), hn3);
            float2 dv = funpack2(dacc);
            float2 qv = funpack2(acc2[k]);
            float2 rv = funpack2(red2[slot][k * 32 + lane]);
            float lx = dv.x - qv.x - rv.x;
            float ly = dv.y - qv.y - rv.y;
            float* xp = &g_h[(size_t)n * 256 + k * 64 + c0];
            float2 xv = *(const float2*)xp;
            xv.x -= fmaxf(lx, 0.f);
            xv.y -= fmaxf(ly, 0.f);
            *(float2*)xp = xv;
        }
    }
}

// ---------------- launch ----------------
extern "C" void kernel_launch(void* const* d_in, const int* in_sizes, int n_in,
                              void* d_out, int out_size)
{
    const float* x    = (const float*)d_in[0];
    const int*   ei   = (const int*)  d_in[1];
    const float* Win1 = (const float*)d_in[2];
    const float* bin1 = (const float*)d_in[3];
    const float* Win2 = (const float*)d_in[4];
    const float* bin2 = (const float*)d_in[5];
    const float* Wm1  = (const float*)d_in[6];
    const float* bm1  = (const float*)d_in[7];
    const float* Wm2  = (const float*)d_in[8];
    const float* bm2  = (const float*)d_in[9];
    const float* Wd1  = (const float*)d_in[10];
    const float* Wd2  = (const float*)d_in[11];
    const float* Wo1  = (const float*)d_in[12];
    const float* bo1  = (const float*)d_in[13];
    const float* Wo2  = (const float*)d_in[14];
    const float* bo2  = (const float*)d_in[15];
    float* out = (float*)d_out;

    void *p_zs, *p_h, *p_h1, *p_AB, *p_Wc, *p_bc;
    cudaGetSymbolAddress(&p_zs, g_zs);
    cudaGetSymbolAddress(&p_h,  g_h);
    cudaGetSymbolAddress(&p_h1, g_h1);
    cudaGetSymbolAddress(&p_AB, g_AB);
    cudaGetSymbolAddress(&p_Wc, g_Wc);
    cudaGetSymbolAddress(&p_bc, g_bc);
    float* h   = (float*)p_h;
    float* h1  = (float*)p_h1;
    float* AB  = (float*)p_AB;
    float* Wc  = (float*)p_Wc;
    float* bc  = (float*)p_bc;

    const int MB = (N_NODES + 127) / 128;  // 157

    // slot 1: h1 = relu(x@Win1^T + bin1)
    sgemm128<true ><<<dim3(1, MB), 256>>>(x, Win1, bin1, h1, N_NODES, 64, IN_DIM);
    // slot 2: h = h1@Win2^T + bin2
    sgemm128<false><<<dim3(4, MB), 256>>>(h1, Win2, bin2, h, N_NODES, 256, 64);
    // slot 3: zero cnt + D
    cudaMemsetAsync(p_zs, 0, sizeof(ZS), 0);
    // slot 4: combined weights
    wc_kernel<<<128, 256>>>(Wm1, Win2, bin2);
    // slot 5 (PROFILED): hcomp layer 0
    hcomp_kernel<<<N_NODES / 8, 256>>>(Wd1, Wd2, 0);
    // AB = h1 @ Wc^T + bc
    sgemm128<false><<<dim3(2, MB), 256>>>(h1, Wc, bc, AB, N_NODES, 128, 64);
    // per-edge Q/Q^T + D atomics
    edge_kernel<<<N_EDGES / 8, 256>>>(ei, Wm2, bm1, bm2);

    // CSR build
    count_kernel<<<(N_EDGES + 255) / 256, 256>>>(ei);
    scan_kernel<<<1, 1024>>>();
    fill_kernel<<<(N_EDGES + 255) / 256, 256>>>(ei);

    // diffusion
    gather_kernel<<<N_NODES / 4, 256>>>(ei);           // layer 0 (hcomp already done)
    hcomp_kernel<<<N_NODES / 8, 256>>>(Wd1, Wd2, 1);   // layer 1
    gather_kernel<<<N_NODES / 4, 256>>>(ei);

    // output MLP
    sgemm128<true ><<<dim3(1, MB), 256>>>(h,  Wo1, bo1, h1,  N_NODES, 64, 256);
    sgemm128<false><<<dim3(1, MB), 256>>>(h1, Wo2, bo2, out, N_NODES, 16, 64);
}

// round 6
// speedup vs baseline: 1.1287x; 1.1287x over previous
#include <cuda_runtime.h>
#include <cuda_bf16.h>

#define N_NODES 20000
#define N_EDGES 200000
#define IN_DIM  500
#define HID     256
#define OUT_DIM 16
#define MHD     64

// ---------------- device scratch (static, no allocations) ----------------
struct ZS {                     // zeroed by ONE memset each launch
    int   cnt[N_NODES];
    float D[N_NODES * 16];      // per-node sum of P (as src) + S (as dst); symmetric
};
__device__ ZS    g_zs;
__device__ float g_h  [N_NODES * HID];     // h, then xb (updated in place)
__device__ float g_h1 [N_NODES * MHD];     // MLP intermediates
__device__ float g_AB [N_NODES * 2 * MHD]; // [N][128]: A | B
__device__ float g_Wc [2 * MHD * MHD];     // combined (Wab @ Win2) -> [128][64]
__device__ float g_bc [2 * MHD];           // combined bias Wab @ bin2
__device__ float g_Q  [(size_t)N_EDGES * 32]; // per edge: Q row-major [0..15], Q^T row-major [16..31]
__device__ float g_H  [N_NODES * HID];     // diffusion operand H per layer
__device__ int   g_off[N_NODES + 1];
__device__ int   g_cur[N_NODES];
__device__ int2  g_incid[2 * N_EDGES];     // {(e<<1)|role, other}

// ---------------- SGEMM: C = act(A[M,K] @ W[N,K]^T + b)  (R4 version) ----
template<bool RELU>
__global__ __launch_bounds__(256)
void sgemm128(const float* __restrict__ A, const float* __restrict__ W,
              const float* __restrict__ bias, float* __restrict__ C,
              int M, int N, int K)
{
    __shared__ float As[16][132];
    __shared__ float Ws[16][68];

    int tid = threadIdx.x;
    int tx = tid & 15, ty = tid >> 4;
    int row0 = blockIdx.y * 128, col0 = blockIdx.x * 64;

    int arow = tid >> 1;
    int akb  = (tid & 1) * 8;
    int wcol = tid & 63;
    int wkb  = (tid >> 6) * 4;

    int gr = row0 + arow;
    int gc = col0 + wcol;
    const float* Arow = A + (size_t)(gr < M ? gr : 0) * K;
    const float* Wrow = W + (size_t)(gc < N ? gc : 0) * K;
    bool rok = gr < M;
    bool cok = gc < N;

    float acc[8][4] = {};
    float ra[8], rw[4];

    #pragma unroll
    for (int u = 0; u < 8; u++) {
        int k = akb + u;
        ra[u] = (rok && k < K) ? Arow[k] : 0.f;
    }
    #pragma unroll
    for (int u = 0; u < 4; u++) {
        int k = wkb + u;
        rw[u] = (cok && k < K) ? Wrow[k] : 0.f;
    }

    for (int k0 = 0; k0 < K; k0 += 16) {
        #pragma unroll
        for (int u = 0; u < 8; u++) As[akb + u][arow] = ra[u];
        #pragma unroll
        for (int u = 0; u < 4; u++) Ws[wkb + u][wcol] = rw[u];
        __syncthreads();

        int kn = k0 + 16;
        if (kn < K) {
            #pragma unroll
            for (int u = 0; u < 8; u++) {
                int k = kn + akb + u;
                ra[u] = (rok && k < K) ? Arow[k] : 0.f;
            }
            #pragma unroll
            for (int u = 0; u < 4; u++) {
                int k = kn + wkb + u;
                rw[u] = (cok && k < K) ? Wrow[k] : 0.f;
            }
        }

        #pragma unroll
        for (int kk = 0; kk < 16; kk++) {
            float4 a0 = *(const float4*)&As[kk][ty * 8];
            float4 a1 = *(const float4*)&As[kk][ty * 8 + 4];
            float4 b0 = *(const float4*)&Ws[kk][tx * 4];
            float a[8] = {a0.x, a0.y, a0.z, a0.w, a1.x, a1.y, a1.z, a1.w};
            float b[4] = {b0.x, b0.y, b0.z, b0.w};
            #pragma unroll
            for (int i = 0; i < 8; i++)
                #pragma unroll
                for (int j = 0; j < 4; j++)
                    acc[i][j] += a[i] * b[j];
        }
        __syncthreads();
    }

    #pragma unroll
    for (int i = 0; i < 8; i++) {
        int r = row0 + ty * 8 + i;
        if (r >= M) continue;
        #pragma unroll
        for (int j = 0; j < 4; j++) {
            int c = col0 + tx * 4 + j;
            if (c >= N) continue;
            float v = acc[i][j] + (bias ? bias[c] : 0.f);
            if (RELU) v = fmaxf(v, 0.f);
            C[(size_t)r * N + c] = v;
        }
    }
}

// ---------------- CSR build ----------------
__global__ void count_kernel(const int* __restrict__ ei) {
    int e = blockIdx.x * 256 + threadIdx.x;
    if (e < N_EDGES) {
        atomicAdd(&g_zs.cnt[ei[e]], 1);
        atomicAdd(&g_zs.cnt[ei[N_EDGES + e]], 1);
    }
}

__global__ void scan_kernel() {
    const int CH = (N_NODES + 1023) / 1024;  // 20
    __shared__ int ssum[1024];
    int tid = threadIdx.x;
    int begin = tid * CH;
    int endi = begin + CH; if (endi > N_NODES) endi = N_NODES;
    int s = 0;
    for (int i = begin; i < endi; i++) s += g_zs.cnt[i];
    ssum[tid] = s;
    __syncthreads();
    for (int off = 1; off < 1024; off <<= 1) {
        int v = 0;
        if (tid >= off) v = ssum[tid - off];
        __syncthreads();
        ssum[tid] += v;
        __syncthreads();
    }
    int run = ssum[tid] - s;
    for (int i = begin; i < endi; i++) {
        g_off[i] = run;
        g_cur[i] = run;
        run += g_zs.cnt[i];
    }
    if (tid == 1023) g_off[N_NODES] = ssum[1023];
}

__global__ void fill_kernel(const int* __restrict__ ei) {
    int e = blockIdx.x * 256 + threadIdx.x;
    if (e < N_EDGES) {
        int s = ei[e], d = ei[N_EDGES + e];
        int p = atomicAdd(&g_cur[s], 1);
        g_incid[p] = make_int2(e << 1, d);         // node is src, other = dst
        int p2 = atomicAdd(&g_cur[d], 1);
        g_incid[p2] = make_int2((e << 1) | 1, s);  // node is dst, other = src
    }
}

// ---------------- combined weights: Wc = Wab @ Win2, bc = Wab @ bin2 -----
__global__ __launch_bounds__(256)
void wc_kernel(const float* __restrict__ Wm1,
               const float* __restrict__ Win2,
               const float* __restrict__ bin2)
{
    __shared__ float part[256];
    __shared__ float bpart[64];
    int i = blockIdx.x;                  // 0..127
    const float* wrow = (i < 64) ? &Wm1[i * 512] : &Wm1[(i - 64) * 512 + 256];
    int t = threadIdx.x;
    int mh = t & 63, kq = t >> 6;
    float s = 0.f;
    #pragma unroll 16
    for (int k = kq * 64; k < kq * 64 + 64; k++)
        s += wrow[k] * Win2[k * 64 + mh];
    part[t] = s;
    if (kq == 0) {
        float b = 0.f;
        #pragma unroll
        for (int k = mh * 4; k < mh * 4 + 4; k++) b += wrow[k] * bin2[k];
        bpart[mh] = b;
    }
    __syncthreads();
    if (kq == 0)
        g_Wc[i * 64 + mh] = part[mh] + part[64 + mh] + part[128 + mh] + part[192 + mh];
    if (t == 0) {
        float bb = 0.f;
        #pragma unroll
        for (int k = 0; k < 64; k++) bb += bpart[k];
        g_bc[i] = bb;
    }
}

// ---------------- per-edge: Q & Q^T stored; P,S atomics into symmetric D
__global__ __launch_bounds__(256)
void edge_kernel(const int* __restrict__ ei, const float* __restrict__ Wm2,
                 const float* __restrict__ bm1, const float* __restrict__ bm2)
{
    __shared__ float W4s[1024];      // Wm2 repacked: [(k>>2)][o][k&3]
    __shared__ float bm2s[16];
    __shared__ float sbuf[8 * 160];  // per warp: t1[64] t2[64] fsft[32]
    int tid = threadIdx.x;
    for (int idx = tid; idx < 1024; idx += 256) {
        int o = idx >> 6, k = idx & 63;
        W4s[((k >> 2) << 6) + (o << 2) + (k & 3)] = Wm2[idx];
    }
    if (tid < 16) bm2s[tid] = bm2[tid];
    __syncthreads();

    int warp = tid >> 5, lane = tid & 31;
    int e = blockIdx.x * 8 + warp;   // grid 25000, exact
    float* sw = &sbuf[warp * 160];

    int s = ei[e], d = ei[N_EDGES + e];
    int k0 = lane * 2;
    float2 As = *(const float2*)&g_AB[s * 128 + k0];
    float2 Bd = *(const float2*)&g_AB[d * 128 + 64 + k0];
    float2 Ad = *(const float2*)&g_AB[d * 128 + k0];
    float2 Bs = *(const float2*)&g_AB[s * 128 + 64 + k0];
    float2 b1 = *(const float2*)&bm1[k0];
    sw[k0]          = fmaxf(As.x + Bd.x + b1.x, 0.f);
    sw[k0 + 1]      = fmaxf(As.y + Bd.y + b1.y, 0.f);
    sw[64 + k0]     = fmaxf(Ad.x + Bs.x + b1.x, 0.f);
    sw[64 + k0 + 1] = fmaxf(Ad.y + Bs.y + b1.y, 0.f);
    __syncwarp();

    // lanes 0-15 -> fs[o] from t1; lanes 16-31 -> ft[o] from t2
    int o = lane & 15;
    const float* tv = sw + ((lane >> 4) << 6);
    float accf = 0.f;
    #pragma unroll
    for (int kc = 0; kc < 16; kc++) {
        float4 t = *(const float4*)&tv[kc * 4];
        float4 w = *(const float4*)&W4s[kc * 64 + o * 4];
        accf += t.x * w.x + t.y * w.y + t.z * w.z + t.w * w.w;
    }
    accf += bm2s[o];
    sw[128 + lane] = accf;
    __syncwarp();

    if (lane < 16) {
        int i = lane >> 2, j = lane & 3;
        float p = 0.f, q = 0.f, ss = 0.f;
        #pragma unroll
        for (int m = 0; m < 4; m++) {
            float fsi = sw[128 + m * 4 + i], fsj = sw[128 + m * 4 + j];
            float fti = sw[144 + m * 4 + i], ftj = sw[144 + m * 4 + j];
            p  += fsi * fsj;   // P = Fs^T Fs  (symmetric)
            q  += fsi * ftj;   // Q = Fs^T Ft
            ss += fti * ftj;   // S = Ft^T Ft  (symmetric)
        }
        float* qb = &g_Q[(size_t)e * 32];
        qb[lane] = q;                          // Q  row-major [i][j]
        qb[16 + j * 4 + i] = q;                // Q^T row-major [j][i]
        atomicAdd(&g_zs.D[s * 16 + lane], p);
        atomicAdd(&g_zs.D[d * 16 + lane], ss);
    }
}

// ---------------- per-node H = (Wd1^T @ xb) @ Wd2^T  (R4 version) --------
__global__ __launch_bounds__(256)
void hcomp_kernel(const float* __restrict__ Wd1, const float* __restrict__ Wd2,
                  int layer)
{
    __shared__ float w2t[64][66];
    __shared__ float h1s[8][4][64];
    int tid = threadIdx.x;
    for (int idx = tid; idx < 4096; idx += 256) {
        int g = idx >> 6, f = idx & 63;
        w2t[f][g] = Wd2[layer * 4096 + idx];
    }
    float wd1[16];
    #pragma unroll
    for (int i = 0; i < 16; i++) wd1[i] = __ldg(&Wd1[layer * 16 + i]);

    int warp = tid >> 5, lane = tid & 31;
    int n = blockIdx.x * 8 + warp;   // grid 2500, exact
    int c0 = lane * 2;
    float2 xv[4];
    #pragma unroll
    for (int j = 0; j < 4; j++)
        xv[j] = *(const float2*)&g_h[n * 256 + j * 64 + c0];
    #pragma unroll
    for (int i = 0; i < 4; i++) {
        h1s[warp][i][c0]     = wd1[i] * xv[0].x + wd1[4 + i] * xv[1].x +
                               wd1[8 + i] * xv[2].x + wd1[12 + i] * xv[3].x;
        h1s[warp][i][c0 + 1] = wd1[i] * xv[0].y + wd1[4 + i] * xv[1].y +
                               wd1[8 + i] * xv[2].y + wd1[12 + i] * xv[3].y;
    }
    __syncthreads();

    float2 acc[4] = {{0,0},{0,0},{0,0},{0,0}};
    #pragma unroll
    for (int f = 0; f < 64; f++) {
        float2 w = *(const float2*)&w2t[f][c0];
        #pragma unroll
        for (int k = 0; k < 4; k++) {
            float hv = h1s[warp][k][f];
            acc[k].x += hv * w.x;
            acc[k].y += hv * w.y;
        }
    }
    #pragma unroll
    for (int k = 0; k < 4; k++)
        *(float2*)&g_H[n * 256 + k * 64 + c0] = acc[k];
}

// ---------------- gather v2: 5 LDG per incidence, deferred butterfly -----
// Lane layout: g = lane>>4 (0/1), cl = lane&15. Lane owns cols cl*4..cl*4+3
// and H k-rows {g, g+2}. part[i][c'] accumulates Qeff-col products over its
// two j's; final shfl-xor-16 butterfly completes the j-sum.
__device__ __forceinline__ void proc_inc2(int idx, int g, int cl, float part[4][4])
{
    int2 v = __ldg(&g_incid[idx]);
    int e = v.x >> 1, role = v.x & 1;
    int other = v.y;
    // role=0: Qeff=Q, need Q cols -> Q^T rows (offset 16). role=1: Qeff=Q^T -> Q rows.
    const float* qb = &g_Q[(size_t)e * 32 + (role ? 0 : 16)];
    const float* hb = &g_H[(size_t)other * 256 + cl * 4];

    #pragma unroll
    for (int jj = 0; jj < 2; jj++) {
        int j = g + jj * 2;
        float4 qv = *(const float4*)&qb[j * 4];       // Qeff[0..3][j]
        float4 hv = *(const float4*)&hb[j * 64];      // H[other][j][cols]
        part[0][0] += qv.x * hv.x; part[0][1] += qv.x * hv.y;
        part[0][2] += qv.x * hv.z; part[0][3] += qv.x * hv.w;
        part[1][0] += qv.y * hv.x; part[1][1] += qv.y * hv.y;
        part[1][2] += qv.y * hv.z; part[1][3] += qv.y * hv.w;
        part[2][0] += qv.z * hv.x; part[2][1] += qv.z * hv.y;
        part[2][2] += qv.z * hv.z; part[2][3] += qv.z * hv.w;
        part[3][0] += qv.w * hv.x; part[3][1] += qv.w * hv.y;
        part[3][2] += qv.w * hv.z; part[3][3] += qv.w * hv.w;
    }
}

__global__ __launch_bounds__(256)
void gather_kernel()
{
    __shared__ float red[4][32][16];   // per slot: per lane 16 partials (8KB)
    int warp = threadIdx.x >> 5, lane = threadIdx.x & 31;
    int slot = warp >> 1, w2 = warp & 1;
    int n = blockIdx.x * 4 + slot;     // grid 5000, exact
    int beg = g_off[n], endi = g_off[n + 1];
    int cnt = endi - beg;
    int mid = beg + ((cnt + 1) >> 1);
    int lo = w2 ? mid : beg;
    int hi = w2 ? endi : mid;
    int g = lane >> 4, cl = lane & 15;

    float part[4][4] = {};

    int idx = lo;
    for (; idx + 1 < hi; idx += 2) {
        proc_inc2(idx,     g, cl, part);
        proc_inc2(idx + 1, g, cl, part);
    }
    if (idx < hi) proc_inc2(idx, g, cl, part);

    if (w2) {
        #pragma unroll
        for (int i = 0; i < 4; i++)
            #pragma unroll
            for (int c = 0; c < 4; c++)
                red[slot][lane][i * 4 + c] = part[i][c];
    }
    __syncthreads();
    if (!w2) {
        // add sibling warp's partials (same lane -> same j-subset)
        #pragma unroll
        for (int i = 0; i < 4; i++)
            #pragma unroll
            for (int c = 0; c < 4; c++)
                part[i][c] += red[slot][lane][i * 4 + c];

        // D-term (symmetric D: rows == cols), same j-subset; LH = D*Hn - Qsum
        const float* db = &g_zs.D[n * 16];
        const float* hb = &g_H[(size_t)n * 256 + cl * 4];
        float lh[4][4];
        {
            float4 qv0 = *(const float4*)&db[g * 4];
            float4 hv0 = *(const float4*)&hb[g * 64];
            float4 qv1 = *(const float4*)&db[(g + 2) * 4];
            float4 hv1 = *(const float4*)&hb[(g + 2) * 64];
            #pragma unroll
            for (int i = 0; i < 4; i++) {
                float qi0 = (i == 0 ? qv0.x : i == 1 ? qv0.y : i == 2 ? qv0.z : qv0.w);
                float qi1 = (i == 0 ? qv1.x : i == 1 ? qv1.y : i == 2 ? qv1.z : qv1.w);
                lh[i][0] = qi0 * hv0.x + qi1 * hv1.x - part[i][0];
                lh[i][1] = qi0 * hv0.y + qi1 * hv1.y - part[i][1];
                lh[i][2] = qi0 * hv0.z + qi1 * hv1.z - part[i][2];
                lh[i][3] = qi0 * hv0.w + qi1 * hv1.w - part[i][3];
            }
        }
        // butterfly across groups: combine j-subsets {g,g+2} and {1-g,3-g}
        #pragma unroll
        for (int i = 0; i < 4; i++)
            #pragma unroll
            for (int c = 0; c < 4; c++)
                lh[i][c] += __shfl_xor_sync(0xffffffffu, lh[i][c], 16);

        // writeback: lanes 0-15 rows {0,1}, lanes 16-31 rows {2,3}
        #pragma unroll
        for (int r = 0; r < 2; r++) {
            int i = g * 2 + r;
            float* xp = &g_h[(size_t)n * 256 + i * 64 + cl * 4];
            float4 xv = *(const float4*)xp;
            xv.x -= fmaxf(lh[i][0], 0.f);
            xv.y -= fmaxf(lh[i][1], 0.f);
            xv.z -= fmaxf(lh[i][2], 0.f);
            xv.w -= fmaxf(lh[i][3], 0.f);
            *(float4*)xp = xv;
        }
    }
}

// ---------------- launch ----------------
extern "C" void kernel_launch(void* const* d_in, const int* in_sizes, int n_in,
                              void* d_out, int out_size)
{
    const float* x    = (const float*)d_in[0];
    const int*   ei   = (const int*)  d_in[1];
    const float* Win1 = (const float*)d_in[2];
    const float* bin1 = (const float*)d_in[3];
    const float* Win2 = (const float*)d_in[4];
    const float* bin2 = (const float*)d_in[5];
    const float* Wm1  = (const float*)d_in[6];
    const float* bm1  = (const float*)d_in[7];
    const float* Wm2  = (const float*)d_in[8];
    const float* bm2  = (const float*)d_in[9];
    const float* Wd1  = (const float*)d_in[10];
    const float* Wd2  = (const float*)d_in[11];
    const float* Wo1  = (const float*)d_in[12];
    const float* bo1  = (const float*)d_in[13];
    const float* Wo2  = (const float*)d_in[14];
    const float* bo2  = (const float*)d_in[15];
    float* out = (float*)d_out;

    void *p_zs, *p_h, *p_h1, *p_AB, *p_Wc, *p_bc;
    cudaGetSymbolAddress(&p_zs, g_zs);
    cudaGetSymbolAddress(&p_h,  g_h);
    cudaGetSymbolAddress(&p_h1, g_h1);
    cudaGetSymbolAddress(&p_AB, g_AB);
    cudaGetSymbolAddress(&p_Wc, g_Wc);
    cudaGetSymbolAddress(&p_bc, g_bc);
    float* h   = (float*)p_h;
    float* h1  = (float*)p_h1;
    float* AB  = (float*)p_AB;
    float* Wc  = (float*)p_Wc;
    float* bc  = (float*)p_bc;

    const int MB = (N_NODES + 127) / 128;  // 157

    // slot 1: combined weights
    wc_kernel<<<128, 256>>>(Wm1, Win2, bin2);
    // slot 2: h1 = relu(x@Win1^T + bin1)
    sgemm128<true ><<<dim3(1, MB), 256>>>(x, Win1, bin1, h1, N_NODES, 64, IN_DIM);
    // slot 3: zero cnt + D
    cudaMemsetAsync(p_zs, 0, sizeof(ZS), 0);
    // slot 4: AB = h1 @ Wc^T + bc
    sgemm128<false><<<dim3(2, MB), 256>>>(h1, Wc, bc, AB, N_NODES, 128, 64);
    // slot 5 (PROFILED): per-edge Q/Q^T + D atomics
    edge_kernel<<<N_EDGES / 8, 256>>>(ei, Wm2, bm1, bm2);

    // CSR build
    count_kernel<<<(N_EDGES + 255) / 256, 256>>>(ei);
    scan_kernel<<<1, 1024>>>();
    fill_kernel<<<(N_EDGES + 255) / 256, 256>>>(ei);

    // h = h1@Win2^T + bin2
    sgemm128<false><<<dim3(4, MB), 256>>>(h1, Win2, bin2, h, N_NODES, 256, 64);

    // diffusion layers
    for (int l = 0; l < 2; l++) {
        hcomp_kernel<<<N_NODES / 8, 256>>>(Wd1, Wd2, l);
        gather_kernel<<<N_NODES / 4, 256>>>();
    }

    // output MLP
    sgemm128<true ><<<dim3(1, MB), 256>>>(h,  Wo1, bo1, h1,  N_NODES, 64, 256);
    sgemm128<false><<<dim3(1, MB), 256>>>(h1, Wo2, bo2, out, N_NODES, 16, 64);
}

// round 7
// speedup vs baseline: 1.1410x; 1.0109x over previous
#include <cuda_runtime.h>
#include <cuda_bf16.h>

#define N_NODES 20000
#define N_EDGES 200000
#define IN_DIM  500
#define HID     256
#define OUT_DIM 16
#define MHD     64

// ---------------- device scratch (static, no allocations) ----------------
struct ZS {                     // zeroed by ONE memset each launch
    int   cnt[N_NODES];
    float D[N_NODES * 16];      // per-node sum of P (src) + S (dst); symmetric
};
__device__ ZS    g_zs;
__device__ float g_h  [N_NODES * HID];     // h, then xb (updated in place)
__device__ float g_h1 [N_NODES * MHD];     // MLP intermediates
__device__ float g_p0 [N_NODES * MHD];     // split-K partials for input MLP
__device__ float g_p1 [N_NODES * MHD];
__device__ float g_AB [N_NODES * 2 * MHD]; // [N][128]: A | B
__device__ float g_Wc [2 * MHD * MHD];     // combined (Wab @ Win2) -> [128][64]
__device__ float g_bc [2 * MHD];           // combined bias Wab @ bin2
__device__ float g_Q  [(size_t)N_EDGES * 32]; // per edge: Q row-major, Q^T row-major
__device__ float g_H  [N_NODES * HID];     // diffusion operand H per layer
__device__ int   g_off[N_NODES + 1];
__device__ int   g_cur[N_NODES];
__device__ int2  g_incid[2 * N_EDGES];     // {(e<<1)|role, other}

// ---------------- SGEMM: C = act(A[M,K](lda) @ W[N,K](ldw)^T + b) --------
template<bool RELU>
__global__ __launch_bounds__(256, 2)
void sgemm128(const float* __restrict__ A, const float* __restrict__ W,
              const float* __restrict__ bias, float* __restrict__ C,
              int M, int N, int K, int lda, int ldw)
{
    __shared__ float As[16][132];
    __shared__ float Ws[16][68];

    int tid = threadIdx.x;
    int tx = tid & 15, ty = tid >> 4;
    int row0 = blockIdx.y * 128, col0 = blockIdx.x * 64;

    int arow = tid >> 1;
    int akb  = (tid & 1) * 8;
    int wcol = tid & 63;
    int wkb  = (tid >> 6) * 4;

    int gr = row0 + arow;
    int gc = col0 + wcol;
    const float* Arow = A + (size_t)(gr < M ? gr : 0) * lda;
    const float* Wrow = W + (size_t)(gc < N ? gc : 0) * ldw;
    bool rok = gr < M;
    bool cok = gc < N;

    float acc[8][4] = {};
    float ra[8], rw[4];

    #pragma unroll
    for (int u = 0; u < 8; u++) {
        int k = akb + u;
        ra[u] = (rok && k < K) ? Arow[k] : 0.f;
    }
    #pragma unroll
    for (int u = 0; u < 4; u++) {
        int k = wkb + u;
        rw[u] = (cok && k < K) ? Wrow[k] : 0.f;
    }

    for (int k0 = 0; k0 < K; k0 += 16) {
        #pragma unroll
        for (int u = 0; u < 8; u++) As[akb + u][arow] = ra[u];
        #pragma unroll
        for (int u = 0; u < 4; u++) Ws[wkb + u][wcol] = rw[u];
        __syncthreads();

        int kn = k0 + 16;
        if (kn < K) {
            #pragma unroll
            for (int u = 0; u < 8; u++) {
                int k = kn + akb + u;
                ra[u] = (rok && k < K) ? Arow[k] : 0.f;
            }
            #pragma unroll
            for (int u = 0; u < 4; u++) {
                int k = kn + wkb + u;
                rw[u] = (cok && k < K) ? Wrow[k] : 0.f;
            }
        }

        #pragma unroll
        for (int kk = 0; kk < 16; kk++) {
            float4 a0 = *(const float4*)&As[kk][ty * 8];
            float4 a1 = *(const float4*)&As[kk][ty * 8 + 4];
            float4 b0 = *(const float4*)&Ws[kk][tx * 4];
            float a[8] = {a0.x, a0.y, a0.z, a0.w, a1.x, a1.y, a1.z, a1.w};
            float b[4] = {b0.x, b0.y, b0.z, b0.w};
            #pragma unroll
            for (int i = 0; i < 8; i++)
                #pragma unroll
                for (int j = 0; j < 4; j++)
                    acc[i][j] += a[i] * b[j];
        }
        __syncthreads();
    }

    #pragma unroll
    for (int i = 0; i < 8; i++) {
        int r = row0 + ty * 8 + i;
        if (r >= M) continue;
        #pragma unroll
        for (int j = 0; j < 4; j++) {
            int c = col0 + tx * 4 + j;
            if (c >= N) continue;
            float v = acc[i][j] + (bias ? bias[c] : 0.f);
            if (RELU) v = fmaxf(v, 0.f);
            C[(size_t)r * N + c] = v;
        }
    }
}

// ---------------- combine split-K partials: h1 = relu(p0+p1+bias) --------
__global__ __launch_bounds__(256)
void combine_kernel(const float* __restrict__ bias)
{
    int i = blockIdx.x * 256 + threadIdx.x;    // float4 index, < 320000
    float4 a = ((const float4*)g_p0)[i];
    float4 b = ((const float4*)g_p1)[i];
    float4 bs = *(const float4*)&bias[(i * 4) & 63];
    float4 r;
    r.x = fmaxf(a.x + b.x + bs.x, 0.f);
    r.y = fmaxf(a.y + b.y + bs.y, 0.f);
    r.z = fmaxf(a.z + b.z + bs.z, 0.f);
    r.w = fmaxf(a.w + b.w + bs.w, 0.f);
    ((float4*)g_h1)[i] = r;
}

// ---------------- CSR scan + fill ----------------
__global__ void scan_kernel() {
    const int CH = (N_NODES + 1023) / 1024;  // 20
    __shared__ int ssum[1024];
    int tid = threadIdx.x;
    int begin = tid * CH;
    int endi = begin + CH; if (endi > N_NODES) endi = N_NODES;
    int s = 0;
    for (int i = begin; i < endi; i++) s += g_zs.cnt[i];
    ssum[tid] = s;
    __syncthreads();
    for (int off = 1; off < 1024; off <<= 1) {
        int v = 0;
        if (tid >= off) v = ssum[tid - off];
        __syncthreads();
        ssum[tid] += v;
        __syncthreads();
    }
    int run = ssum[tid] - s;
    for (int i = begin; i < endi; i++) {
        g_off[i] = run;
        g_cur[i] = run;
        run += g_zs.cnt[i];
    }
    if (tid == 1023) g_off[N_NODES] = ssum[1023];
}

__global__ void fill_kernel(const int* __restrict__ ei) {
    int e = blockIdx.x * 256 + threadIdx.x;
    if (e < N_EDGES) {
        int s = ei[e], d = ei[N_EDGES + e];
        int p = atomicAdd(&g_cur[s], 1);
        g_incid[p] = make_int2(e << 1, d);         // node is src, other = dst
        int p2 = atomicAdd(&g_cur[d], 1);
        g_incid[p2] = make_int2((e << 1) | 1, s);  // node is dst, other = src
    }
}

// ---------------- combined weights: Wc = Wab @ Win2, bc = Wab @ bin2 -----
__global__ __launch_bounds__(256)
void wc_kernel(const float* __restrict__ Wm1,
               const float* __restrict__ Win2,
               const float* __restrict__ bin2)
{
    __shared__ float part[256];
    __shared__ float bpart[64];
    int i = blockIdx.x;                  // 0..127
    const float* wrow = (i < 64) ? &Wm1[i * 512] : &Wm1[(i - 64) * 512 + 256];
    int t = threadIdx.x;
    int mh = t & 63, kq = t >> 6;
    float s = 0.f;
    #pragma unroll 16
    for (int k = kq * 64; k < kq * 64 + 64; k++)
        s += wrow[k] * Win2[k * 64 + mh];
    part[t] = s;
    if (kq == 0) {
        float b = 0.f;
        #pragma unroll
        for (int k = mh * 4; k < mh * 4 + 4; k++) b += wrow[k] * bin2[k];
        bpart[mh] = b;
    }
    __syncthreads();
    if (kq == 0)
        g_Wc[i * 64 + mh] = part[mh] + part[64 + mh] + part[128 + mh] + part[192 + mh];
    if (t == 0) {
        float bb = 0.f;
        #pragma unroll
        for (int k = 0; k < 64; k++) bb += bpart[k];
        g_bc[i] = bb;
    }
}

// ---------------- per-edge: Q & Q^T; P,S atomics into D; cnt atomics -----
__global__ __launch_bounds__(256)
void edge_kernel(const int* __restrict__ ei, const float* __restrict__ Wm2,
                 const float* __restrict__ bm1, const float* __restrict__ bm2)
{
    __shared__ float W4s[1024];      // Wm2 repacked: [(k>>2)][o][k&3]
    __shared__ float bm2s[16];
    __shared__ float sbuf[8 * 160];  // per warp: t1[64] t2[64] fsft[32]
    int tid = threadIdx.x;
    for (int idx = tid; idx < 1024; idx += 256) {
        int o = idx >> 6, k = idx & 63;
        W4s[((k >> 2) << 6) + (o << 2) + (k & 3)] = Wm2[idx];
    }
    if (tid < 16) bm2s[tid] = bm2[tid];
    __syncthreads();

    int warp = tid >> 5, lane = tid & 31;
    int e = blockIdx.x * 8 + warp;   // grid 25000, exact
    float* sw = &sbuf[warp * 160];

    int s = ei[e], d = ei[N_EDGES + e];
    int k0 = lane * 2;
    float2 As = *(const float2*)&g_AB[s * 128 + k0];
    float2 Bd = *(const float2*)&g_AB[d * 128 + 64 + k0];
    float2 Ad = *(const float2*)&g_AB[d * 128 + k0];
    float2 Bs = *(const float2*)&g_AB[s * 128 + 64 + k0];
    float2 b1 = *(const float2*)&bm1[k0];
    sw[k0]          = fmaxf(As.x + Bd.x + b1.x, 0.f);
    sw[k0 + 1]      = fmaxf(As.y + Bd.y + b1.y, 0.f);
    sw[64 + k0]     = fmaxf(Ad.x + Bs.x + b1.x, 0.f);
    sw[64 + k0 + 1] = fmaxf(Ad.y + Bs.y + b1.y, 0.f);
    __syncwarp();

    // lanes 0-15 -> fs[o] from t1; lanes 16-31 -> ft[o] from t2
    int o = lane & 15;
    const float* tv = sw + ((lane >> 4) << 6);
    float accf = 0.f;
    #pragma unroll
    for (int kc = 0; kc < 16; kc++) {
        float4 t = *(const float4*)&tv[kc * 4];
        float4 w = *(const float4*)&W4s[kc * 64 + o * 4];
        accf += t.x * w.x + t.y * w.y + t.z * w.z + t.w * w.w;
    }
    accf += bm2s[o];
    sw[128 + lane] = accf;
    __syncwarp();

    if (lane < 16) {
        int i = lane >> 2, j = lane & 3;
        float p = 0.f, q = 0.f, ss = 0.f;
        #pragma unroll
        for (int m = 0; m < 4; m++) {
            float fsi = sw[128 + m * 4 + i], fsj = sw[128 + m * 4 + j];
            float fti = sw[144 + m * 4 + i], ftj = sw[144 + m * 4 + j];
            p  += fsi * fsj;   // P = Fs^T Fs  (symmetric)
            q  += fsi * ftj;   // Q = Fs^T Ft
            ss += fti * ftj;   // S = Ft^T Ft  (symmetric)
        }
        float* qb = &g_Q[(size_t)e * 32];
        qb[lane] = q;                          // Q  row-major [i][j]
        qb[16 + j * 4 + i] = q;                // Q^T row-major [j][i]
        atomicAdd(&g_zs.D[s * 16 + lane], p);
        atomicAdd(&g_zs.D[d * 16 + lane], ss);
    } else if (lane == 16) {
        atomicAdd(&g_zs.cnt[s], 1);            // merged count_kernel
    } else if (lane == 17) {
        atomicAdd(&g_zs.cnt[d], 1);
    }
}

// ---------------- per-node H = (Wd1^T @ xb) @ Wd2^T ----------------------
// Stage 2 reads Wd2 in NATURAL [g][f] layout (pad 65 -> bank = lane+const,
// conflict-free scalar LDS), lane owns output cols {lane, lane+32}.
__global__ __launch_bounds__(256)
void hcomp_kernel(const float* __restrict__ Wd1, const float* __restrict__ Wd2,
                  int layer)
{
    __shared__ float w2s[64 * 65];   // w2s[g*65 + f] = Wd2[l][g][f]
    __shared__ float h1s[8][4][64];
    int tid = threadIdx.x;
    for (int idx = tid; idx < 4096; idx += 256) {
        int g = idx >> 6, f = idx & 63;
        w2s[g * 65 + f] = Wd2[layer * 4096 + idx];
    }
    float wd1[16];
    #pragma unroll
    for (int i = 0; i < 16; i++) wd1[i] = __ldg(&Wd1[layer * 16 + i]);

    int warp = tid >> 5, lane = tid & 31;
    int n = blockIdx.x * 8 + warp;   // grid 2500, exact
    int c0 = lane * 2;
    float2 xv[4];
    #pragma unroll
    for (int j = 0; j < 4; j++)
        xv[j] = *(const float2*)&g_h[n * 256 + j * 64 + c0];
    #pragma unroll
    for (int i = 0; i < 4; i++) {
        h1s[warp][i][c0]     = wd1[i] * xv[0].x + wd1[4 + i] * xv[1].x +
                               wd1[8 + i] * xv[2].x + wd1[12 + i] * xv[3].x;
        h1s[warp][i][c0 + 1] = wd1[i] * xv[0].y + wd1[4 + i] * xv[1].y +
                               wd1[8 + i] * xv[2].y + wd1[12 + i] * xv[3].y;
    }
    __syncthreads();

    int ca = lane, cb = lane + 32;
    float acca[4] = {0, 0, 0, 0};
    float accb[4] = {0, 0, 0, 0};
    #pragma unroll
    for (int f0 = 0; f0 < 64; f0 += 4) {
        float4 h0 = *(const float4*)&h1s[warp][0][f0];
        float4 h1 = *(const float4*)&h1s[warp][1][f0];
        float4 h2 = *(const float4*)&h1s[warp][2][f0];
        float4 h3 = *(const float4*)&h1s[warp][3][f0];
        const float* wa = &w2s[ca * 65 + f0];
        const float* wb = &w2s[cb * 65 + f0];
        float wa0 = wa[0], wa1 = wa[1], wa2 = wa[2], wa3 = wa[3];
        float wb0 = wb[0], wb1 = wb[1], wb2 = wb[2], wb3 = wb[3];
        acca[0] += h0.x * wa0 + h0.y * wa1 + h0.z * wa2 + h0.w * wa3;
        acca[1] += h1.x * wa0 + h1.y * wa1 + h1.z * wa2 + h1.w * wa3;
        acca[2] += h2.x * wa0 + h2.y * wa1 + h2.z * wa2 + h2.w * wa3;
        acca[3] += h3.x * wa0 + h3.y * wa1 + h3.z * wa2 + h3.w * wa3;
        accb[0] += h0.x * wb0 + h0.y * wb1 + h0.z * wb2 + h0.w * wb3;
        accb[1] += h1.x * wb0 + h1.y * wb1 + h1.z * wb2 + h1.w * wb3;
        accb[2] += h2.x * wb0 + h2.y * wb1 + h2.z * wb2 + h2.w * wb3;
        accb[3] += h3.x * wb0 + h3.y * wb1 + h3.z * wb2 + h3.w * wb3;
    }
    #pragma unroll
    for (int k = 0; k < 4; k++) {
        g_H[n * 256 + k * 64 + ca] = acca[k];
        g_H[n * 256 + k * 64 + cb] = accb[k];
    }
}

// ---------------- gather v2: 5 LDG per incidence, deferred butterfly -----
__device__ __forceinline__ void proc_inc2(int idx, int g, int cl, float part[4][4])
{
    int2 v = __ldg(&g_incid[idx]);
    int e = v.x >> 1, role = v.x & 1;
    int other = v.y;
    const float* qb = &g_Q[(size_t)e * 32 + (role ? 0 : 16)];
    const float* hb = &g_H[(size_t)other * 256 + cl * 4];

    #pragma unroll
    for (int jj = 0; jj < 2; jj++) {
        int j = g + jj * 2;
        float4 qv = *(const float4*)&qb[j * 4];
        float4 hv = *(const float4*)&hb[j * 64];
        part[0][0] += qv.x * hv.x; part[0][1] += qv.x * hv.y;
        part[0][2] += qv.x * hv.z; part[0][3] += qv.x * hv.w;
        part[1][0] += qv.y * hv.x; part[1][1] += qv.y * hv.y;
        part[1][2] += qv.y * hv.z; part[1][3] += qv.y * hv.w;
        part[2][0] += qv.z * hv.x; part[2][1] += qv.z * hv.y;
        part[2][2] += qv.z * hv.z; part[2][3] += qv.z * hv.w;
        part[3][0] += qv.w * hv.x; part[3][1] += qv.w * hv.y;
        part[3][2] += qv.w * hv.z; part[3][3] += qv.w * hv.w;
    }
}

__global__ __launch_bounds__(256)
void gather_kernel()
{
    __shared__ float red[4][32][16];
    int warp = threadIdx.x >> 5, lane = threadIdx.x & 31;
    int slot = warp >> 1, w2 = warp & 1;
    int n = blockIdx.x * 4 + slot;     // grid 5000, exact
    int beg = g_off[n], endi = g_off[n + 1];
    int cnt = endi - beg;
    int mid = beg + ((cnt + 1) >> 1);
    int lo = w2 ? mid : beg;
    int hi = w2 ? endi : mid;
    int g = lane >> 4, cl = lane & 15;

    float part[4][4] = {};

    int idx = lo;
    for (; idx + 1 < hi; idx += 2) {
        proc_inc2(idx,     g, cl, part);
        proc_inc2(idx + 1, g, cl, part);
    }
    if (idx < hi) proc_inc2(idx, g, cl, part);

    if (w2) {
        #pragma unroll
        for (int i = 0; i < 4; i++)
            #pragma unroll
            for (int c = 0; c < 4; c++)
                red[slot][lane][i * 4 + c] = part[i][c];
    }
    __syncthreads();
    if (!w2) {
        #pragma unroll
        for (int i = 0; i < 4; i++)
            #pragma unroll
            for (int c = 0; c < 4; c++)
                part[i][c] += red[slot][lane][i * 4 + c];

        const float* db = &g_zs.D[n * 16];
        const float* hb = &g_H[(size_t)n * 256 + cl * 4];
        float lh[4][4];
        {
            float4 qv0 = *(const float4*)&db[g * 4];
            float4 hv0 = *(const float4*)&hb[g * 64];
            float4 qv1 = *(const float4*)&db[(g + 2) * 4];
            float4 hv1 = *(const float4*)&hb[(g + 2) * 64];
            #pragma unroll
            for (int i = 0; i < 4; i++) {
                float qi0 = (i == 0 ? qv0.x : i == 1 ? qv0.y : i == 2 ? qv0.z : qv0.w);
                float qi1 = (i == 0 ? qv1.x : i == 1 ? qv1.y : i == 2 ? qv1.z : qv1.w);
                lh[i][0] = qi0 * hv0.x + qi1 * hv1.x - part[i][0];
                lh[i][1] = qi0 * hv0.y + qi1 * hv1.y - part[i][1];
                lh[i][2] = qi0 * hv0.z + qi1 * hv1.z - part[i][2];
                lh[i][3] = qi0 * hv0.w + qi1 * hv1.w - part[i][3];
            }
        }
        #pragma unroll
        for (int i = 0; i < 4; i++)
            #pragma unroll
            for (int c = 0; c < 4; c++)
                lh[i][c] += __shfl_xor_sync(0xffffffffu, lh[i][c], 16);

        #pragma unroll
        for (int r = 0; r < 2; r++) {
            int i = g * 2 + r;
            float* xp = &g_h[(size_t)n * 256 + i * 64 + cl * 4];
            float4 xv = *(const float4*)xp;
            xv.x -= fmaxf(lh[i][0], 0.f);
            xv.y -= fmaxf(lh[i][1], 0.f);
            xv.z -= fmaxf(lh[i][2], 0.f);
            xv.w -= fmaxf(lh[i][3], 0.f);
            *(float4*)xp = xv;
        }
    }
}

// ---------------- launch ----------------
extern "C" void kernel_launch(void* const* d_in, const int* in_sizes, int n_in,
                              void* d_out, int out_size)
{
    const float* x    = (const float*)d_in[0];
    const int*   ei   = (const int*)  d_in[1];
    const float* Win1 = (const float*)d_in[2];
    const float* bin1 = (const float*)d_in[3];
    const float* Win2 = (const float*)d_in[4];
    const float* bin2 = (const float*)d_in[5];
    const float* Wm1  = (const float*)d_in[6];
    const float* bm1  = (const float*)d_in[7];
    const float* Wm2  = (const float*)d_in[8];
    const float* bm2  = (const float*)d_in[9];
    const float* Wd1  = (const float*)d_in[10];
    const float* Wd2  = (const float*)d_in[11];
    const float* Wo1  = (const float*)d_in[12];
    const float* bo1  = (const float*)d_in[13];
    const float* Wo2  = (const float*)d_in[14];
    const float* bo2  = (const float*)d_in[15];
    float* out = (float*)d_out;

    void *p_zs, *p_h, *p_h1, *p_p0, *p_p1, *p_AB, *p_Wc, *p_bc;
    cudaGetSymbolAddress(&p_zs, g_zs);
    cudaGetSymbolAddress(&p_h,  g_h);
    cudaGetSymbolAddress(&p_h1, g_h1);
    cudaGetSymbolAddress(&p_p0, g_p0);
    cudaGetSymbolAddress(&p_p1, g_p1);
    cudaGetSymbolAddress(&p_AB, g_AB);
    cudaGetSymbolAddress(&p_Wc, g_Wc);
    cudaGetSymbolAddress(&p_bc, g_bc);
    float* h   = (float*)p_h;
    float* h1  = (float*)p_h1;
    float* P0  = (float*)p_p0;
    float* P1  = (float*)p_p1;
    float* AB  = (float*)p_AB;
    float* Wc  = (float*)p_Wc;
    float* bc  = (float*)p_bc;

    const int MB = (N_NODES + 127) / 128;  // 157

    // 0: zero cnt + D
    cudaMemsetAsync(p_zs, 0, sizeof(ZS), 0);
    // 1,2: input MLP stage 1, split-K (K=500 -> 256 + 244), grid 314 total
    sgemm128<false><<<dim3(1, MB), 256>>>(x,       Win1,       nullptr, P0,
                                          N_NODES, 64, 256, IN_DIM, IN_DIM);
    sgemm128<false><<<dim3(1, MB), 256>>>(x + 256, Win1 + 256, nullptr, P1,
                                          N_NODES, 64, 244, IN_DIM, IN_DIM);
    // 3: h1 = relu(P0 + P1 + bin1)
    combine_kernel<<<(N_NODES * 64 / 4 + 255) / 256, 256>>>(bin1);
    // 4 (PROFILED): h = h1 @ Win2^T + bin2
    sgemm128<false><<<dim3(4, MB), 256>>>(h1, Win2, bin2, h, N_NODES, 256, 64, 64, 64);
    // combined weights
    wc_kernel<<<128, 256>>>(Wm1, Win2, bin2);
    // AB = h1 @ Wc^T + bc
    sgemm128<false><<<dim3(2, MB), 256>>>(h1, Wc, bc, AB, N_NODES, 128, 64, 64, 64);
    // per-edge Q/Q^T + D atomics + cnt atomics
    edge_kernel<<<N_EDGES / 8, 256>>>(ei, Wm2, bm1, bm2);

    // CSR scan + fill
    scan_kernel<<<1, 1024>>>();
    fill_kernel<<<(N_EDGES + 255) / 256, 256>>>(ei);

    // diffusion layers
    for (int l = 0; l < 2; l++) {
        hcomp_kernel<<<N_NODES / 8, 256>>>(Wd1, Wd2, l);
        gather_kernel<<<N_NODES / 4, 256>>>();
    }

    // output MLP
    sgemm128<true ><<<dim3(1, MB), 256>>>(h,  Wo1, bo1, h1,  N_NODES, 64, 256, 256, 256);
    sgemm128<false><<<dim3(1, MB), 256>>>(h1, Wo2, bo2, out, N_NODES, 16, 64, 64, 64);
}

// round 8
// speedup vs baseline: 1.2602x; 1.1045x over previous
#include <cuda_runtime.h>
#include <cuda_bf16.h>

#define N_NODES 20000
#define N_EDGES 200000
#define IN_DIM  500
#define HID     256
#define OUT_DIM 16
#define MHD     64

// ---------------- device scratch (static, no allocations) ----------------
struct ZS {                     // zeroed by ONE memset each launch
    int   cnt[N_NODES];
    float D[N_NODES * 16];      // per-node sum of P (src) + S (dst); symmetric
};
__device__ ZS    g_zs;
__device__ float g_h  [N_NODES * HID];     // h, then xb (updated in place)
__device__ float g_h1 [N_NODES * MHD];     // MLP intermediates
__device__ float g_p0 [N_NODES * MHD];     // split-K partials for input MLP
__device__ float g_p1 [N_NODES * MHD];
__device__ float g_AB [N_NODES * 2 * MHD]; // [N][128]: A | B
__device__ float g_Wc [2 * MHD * MHD];     // combined (Wab @ Win2) -> [128][64]
__device__ float g_bc [2 * MHD];           // combined bias Wab @ bin2
__device__ float g_Q  [(size_t)N_EDGES * 32]; // per edge: Q row-major, Q^T row-major
__device__ float g_H  [N_NODES * HID];     // diffusion operand H per layer
__device__ int   g_off[N_NODES + 1];
__device__ int   g_cur[N_NODES];
__device__ int2  g_incid[2 * N_EDGES];     // {(e<<1)|role, other}

// ---------------- SGEMM: C = act(A[M,K](lda) @ W[N,K](ldw)^T + b) --------
template<bool RELU>
__global__ __launch_bounds__(256, 2)
void sgemm128(const float* __restrict__ A, const float* __restrict__ W,
              const float* __restrict__ bias, float* __restrict__ C,
              int M, int N, int K, int lda, int ldw)
{
    __shared__ float As[16][132];
    __shared__ float Ws[16][68];

    int tid = threadIdx.x;
    int tx = tid & 15, ty = tid >> 4;
    int row0 = blockIdx.y * 128, col0 = blockIdx.x * 64;

    int arow = tid >> 1;
    int akb  = (tid & 1) * 8;
    int wcol = tid & 63;
    int wkb  = (tid >> 6) * 4;

    int gr = row0 + arow;
    int gc = col0 + wcol;
    const float* Arow = A + (size_t)(gr < M ? gr : 0) * lda;
    const float* Wrow = W + (size_t)(gc < N ? gc : 0) * ldw;
    bool rok = gr < M;
    bool cok = gc < N;

    float acc[8][4] = {};
    float ra[8], rw[4];

    #pragma unroll
    for (int u = 0; u < 8; u++) {
        int k = akb + u;
        ra[u] = (rok && k < K) ? Arow[k] : 0.f;
    }
    #pragma unroll
    for (int u = 0; u < 4; u++) {
        int k = wkb + u;
        rw[u] = (cok && k < K) ? Wrow[k] : 0.f;
    }

    for (int k0 = 0; k0 < K; k0 += 16) {
        #pragma unroll
        for (int u = 0; u < 8; u++) As[akb + u][arow] = ra[u];
        #pragma unroll
        for (int u = 0; u < 4; u++) Ws[wkb + u][wcol] = rw[u];
        __syncthreads();

        int kn = k0 + 16;
        if (kn < K) {
            #pragma unroll
            for (int u = 0; u < 8; u++) {
                int k = kn + akb + u;
                ra[u] = (rok && k < K) ? Arow[k] : 0.f;
            }
            #pragma unroll
            for (int u = 0; u < 4; u++) {
                int k = kn + wkb + u;
                rw[u] = (cok && k < K) ? Wrow[k] : 0.f;
            }
        }

        #pragma unroll
        for (int kk = 0; kk < 16; kk++) {
            float4 a0 = *(const float4*)&As[kk][ty * 8];
            float4 a1 = *(const float4*)&As[kk][ty * 8 + 4];
            float4 b0 = *(const float4*)&Ws[kk][tx * 4];
            float a[8] = {a0.x, a0.y, a0.z, a0.w, a1.x, a1.y, a1.z, a1.w};
            float b[4] = {b0.x, b0.y, b0.z, b0.w};
            #pragma unroll
            for (int i = 0; i < 8; i++)
                #pragma unroll
                for (int j = 0; j < 4; j++)
                    acc[i][j] += a[i] * b[j];
        }
        __syncthreads();
    }

    #pragma unroll
    for (int i = 0; i < 8; i++) {
        int r = row0 + ty * 8 + i;
        if (r >= M) continue;
        #pragma unroll
        for (int j = 0; j < 4; j++) {
            int c = col0 + tx * 4 + j;
            if (c >= N) continue;
            float v = acc[i][j] + (bias ? bias[c] : 0.f);
            if (RELU) v = fmaxf(v, 0.f);
            C[(size_t)r * N + c] = v;
        }
    }
}

// ---------------- combine split-K partials: h1 = relu(p0+p1+bias) --------
__global__ __launch_bounds__(256)
void combine_kernel(const float* __restrict__ bias)
{
    int i = blockIdx.x * 256 + threadIdx.x;    // float4 index, < 320000
    float4 a = ((const float4*)g_p0)[i];
    float4 b = ((const float4*)g_p1)[i];
    float4 bs = *(const float4*)&bias[(i * 4) & 63];
    float4 r;
    r.x = fmaxf(a.x + b.x + bs.x, 0.f);
    r.y = fmaxf(a.y + b.y + bs.y, 0.f);
    r.z = fmaxf(a.z + b.z + bs.z, 0.f);
    r.w = fmaxf(a.w + b.w + bs.w, 0.f);
    ((float4*)g_h1)[i] = r;
}

// ---------------- CSR build ----------------
__global__ void count_kernel(const int* __restrict__ ei) {
    int e = blockIdx.x * 256 + threadIdx.x;
    if (e < N_EDGES) {
        atomicAdd(&g_zs.cnt[ei[e]], 1);
        atomicAdd(&g_zs.cnt[ei[N_EDGES + e]], 1);
    }
}

__global__ void scan_kernel() {
    const int CH = (N_NODES + 1023) / 1024;  // 20
    __shared__ int ssum[1024];
    int tid = threadIdx.x;
    int begin = tid * CH;
    int endi = begin + CH; if (endi > N_NODES) endi = N_NODES;
    int s = 0;
    for (int i = begin; i < endi; i++) s += g_zs.cnt[i];
    ssum[tid] = s;
    __syncthreads();
    for (int off = 1; off < 1024; off <<= 1) {
        int v = 0;
        if (tid >= off) v = ssum[tid - off];
        __syncthreads();
        ssum[tid] += v;
        __syncthreads();
    }
    int run = ssum[tid] - s;
    for (int i = begin; i < endi; i++) {
        g_off[i] = run;
        g_cur[i] = run;
        run += g_zs.cnt[i];
    }
    if (tid == 1023) g_off[N_NODES] = ssum[1023];
}

__global__ void fill_kernel(const int* __restrict__ ei) {
    int e = blockIdx.x * 256 + threadIdx.x;
    if (e < N_EDGES) {
        int s = ei[e], d = ei[N_EDGES + e];
        int p = atomicAdd(&g_cur[s], 1);
        g_incid[p] = make_int2(e << 1, d);         // node is src, other = dst
        int p2 = atomicAdd(&g_cur[d], 1);
        g_incid[p2] = make_int2((e << 1) | 1, s);  // node is dst, other = src
    }
}

// ---------------- combined weights: Wc = Wab @ Win2, bc = Wab @ bin2 -----
__global__ __launch_bounds__(256)
void wc_kernel(const float* __restrict__ Wm1,
               const float* __restrict__ Win2,
               const float* __restrict__ bin2)
{
    __shared__ float part[256];
    __shared__ float bpart[64];
    int i = blockIdx.x;                  // 0..127
    const float* wrow = (i < 64) ? &Wm1[i * 512] : &Wm1[(i - 64) * 512 + 256];
    int t = threadIdx.x;
    int mh = t & 63, kq = t >> 6;
    float s = 0.f;
    #pragma unroll 16
    for (int k = kq * 64; k < kq * 64 + 64; k++)
        s += wrow[k] * Win2[k * 64 + mh];
    part[t] = s;
    if (kq == 0) {
        float b = 0.f;
        #pragma unroll
        for (int k = mh * 4; k < mh * 4 + 4; k++) b += wrow[k] * bin2[k];
        bpart[mh] = b;
    }
    __syncthreads();
    if (kq == 0)
        g_Wc[i * 64 + mh] = part[mh] + part[64 + mh] + part[128 + mh] + part[192 + mh];
    if (t == 0) {
        float bb = 0.f;
        #pragma unroll
        for (int k = 0; k < 64; k++) bb += bpart[k];
        g_bc[i] = bb;
    }
}

// ---------------- per-edge: Q & Q^T; P,S atomics into D ------------------
__global__ __launch_bounds__(256)
void edge_kernel(const int* __restrict__ ei, const float* __restrict__ Wm2,
                 const float* __restrict__ bm1, const float* __restrict__ bm2)
{
    __shared__ float W4s[1024];      // Wm2 repacked: [(k>>2)][o][k&3]
    __shared__ float bm2s[16];
    __shared__ float sbuf[8 * 160];  // per warp: t1[64] t2[64] fsft[32]
    int tid = threadIdx.x;
    for (int idx = tid; idx < 1024; idx += 256) {
        int o = idx >> 6, k = idx & 63;
        W4s[((k >> 2) << 6) + (o << 2) + (k & 3)] = Wm2[idx];
    }
    if (tid < 16) bm2s[tid] = bm2[tid];
    __syncthreads();

    int warp = tid >> 5, lane = tid & 31;
    int e = blockIdx.x * 8 + warp;   // grid 25000, exact
    float* sw = &sbuf[warp * 160];

    int s = ei[e], d = ei[N_EDGES + e];
    int k0 = lane * 2;
    float2 As = *(const float2*)&g_AB[s * 128 + k0];
    float2 Bd = *(const float2*)&g_AB[d * 128 + 64 + k0];
    float2 Ad = *(const float2*)&g_AB[d * 128 + k0];
    float2 Bs = *(const float2*)&g_AB[s * 128 + 64 + k0];
    float2 b1 = *(const float2*)&bm1[k0];
    sw[k0]          = fmaxf(As.x + Bd.x + b1.x, 0.f);
    sw[k0 + 1]      = fmaxf(As.y + Bd.y + b1.y, 0.f);
    sw[64 + k0]     = fmaxf(Ad.x + Bs.x + b1.x, 0.f);
    sw[64 + k0 + 1] = fmaxf(Ad.y + Bs.y + b1.y, 0.f);
    __syncwarp();

    // lanes 0-15 -> fs[o] from t1; lanes 16-31 -> ft[o] from t2
    int o = lane & 15;
    const float* tv = sw + ((lane >> 4) << 6);
    float accf = 0.f;
    #pragma unroll
    for (int kc = 0; kc < 16; kc++) {
        float4 t = *(const float4*)&tv[kc * 4];
        float4 w = *(const float4*)&W4s[kc * 64 + o * 4];
        accf += t.x * w.x + t.y * w.y + t.z * w.z + t.w * w.w;
    }
    accf += bm2s[o];
    sw[128 + lane] = accf;
    __syncwarp();

    if (lane < 16) {
        int i = lane >> 2, j = lane & 3;
        float p = 0.f, q = 0.f, ss = 0.f;
        #pragma unroll
        for (int m = 0; m < 4; m++) {
            float fsi = sw[128 + m * 4 + i], fsj = sw[128 + m * 4 + j];
            float fti = sw[144 + m * 4 + i], ftj = sw[144 + m * 4 + j];
            p  += fsi * fsj;   // P = Fs^T Fs  (symmetric)
            q  += fsi * ftj;   // Q = Fs^T Ft
            ss += fti * ftj;   // S = Ft^T Ft  (symmetric)
        }
        float* qb = &g_Q[(size_t)e * 32];
        qb[lane] = q;                          // Q  row-major [i][j]
        qb[16 + j * 4 + i] = q;                // Q^T row-major [j][i]
        atomicAdd(&g_zs.D[s * 16 + lane], p);
        atomicAdd(&g_zs.D[d * 16 + lane], ss);
    }
}

// ---------------- per-node H = (Wd1^T @ xb) @ Wd2^T ----------------------
__global__ __launch_bounds__(256)
void hcomp_kernel(const float* __restrict__ Wd1, const float* __restrict__ Wd2,
                  int layer)
{
    __shared__ float w2s[64 * 65];   // w2s[g*65 + f] = Wd2[l][g][f]
    __shared__ float h1s[8][4][64];
    int tid = threadIdx.x;
    for (int idx = tid; idx < 4096; idx += 256) {
        int g = idx >> 6, f = idx & 63;
        w2s[g * 65 + f] = Wd2[layer * 4096 + idx];
    }
    float wd1[16];
    #pragma unroll
    for (int i = 0; i < 16; i++) wd1[i] = __ldg(&Wd1[layer * 16 + i]);

    int warp = tid >> 5, lane = tid & 31;
    int n = blockIdx.x * 8 + warp;   // grid 2500, exact
    int c0 = lane * 2;
    float2 xv[4];
    #pragma unroll
    for (int j = 0; j < 4; j++)
        xv[j] = *(const float2*)&g_h[n * 256 + j * 64 + c0];
    #pragma unroll
    for (int i = 0; i < 4; i++) {
        h1s[warp][i][c0]     = wd1[i] * xv[0].x + wd1[4 + i] * xv[1].x +
                               wd1[8 + i] * xv[2].x + wd1[12 + i] * xv[3].x;
        h1s[warp][i][c0 + 1] = wd1[i] * xv[0].y + wd1[4 + i] * xv[1].y +
                               wd1[8 + i] * xv[2].y + wd1[12 + i] * xv[3].y;
    }
    __syncthreads();

    int ca = lane, cb = lane + 32;
    float acca[4] = {0, 0, 0, 0};
    float accb[4] = {0, 0, 0, 0};
    #pragma unroll
    for (int f0 = 0; f0 < 64; f0 += 4) {
        float4 h0 = *(const float4*)&h1s[warp][0][f0];
        float4 h1 = *(const float4*)&h1s[warp][1][f0];
        float4 h2 = *(const float4*)&h1s[warp][2][f0];
        float4 h3 = *(const float4*)&h1s[warp][3][f0];
        const float* wa = &w2s[ca * 65 + f0];
        const float* wb = &w2s[cb * 65 + f0];
        float wa0 = wa[0], wa1 = wa[1], wa2 = wa[2], wa3 = wa[3];
        float wb0 = wb[0], wb1 = wb[1], wb2 = wb[2], wb3 = wb[3];
        acca[0] += h0.x * wa0 + h0.y * wa1 + h0.z * wa2 + h0.w * wa3;
        acca[1] += h1.x * wa0 + h1.y * wa1 + h1.z * wa2 + h1.w * wa3;
        acca[2] += h2.x * wa0 + h2.y * wa1 + h2.z * wa2 + h2.w * wa3;
        acca[3] += h3.x * wa0 + h3.y * wa1 + h3.z * wa2 + h3.w * wa3;
        accb[0] += h0.x * wb0 + h0.y * wb1 + h0.z * wb2 + h0.w * wb3;
        accb[1] += h1.x * wb0 + h1.y * wb1 + h1.z * wb2 + h1.w * wb3;
        accb[2] += h2.x * wb0 + h2.y * wb1 + h2.z * wb2 + h2.w * wb3;
        accb[3] += h3.x * wb0 + h3.y * wb1 + h3.z * wb2 + h3.w * wb3;
    }
    #pragma unroll
    for (int k = 0; k < 4; k++) {
        g_H[n * 256 + k * 64 + ca] = acca[k];
        g_H[n * 256 + k * 64 + cb] = accb[k];
    }
}

// ---------------- gather: 5 LDG per incidence, deferred butterfly --------
__device__ __forceinline__ void proc_inc2(int idx, int g, int cl, float part[4][4])
{
    int2 v = __ldg(&g_incid[idx]);
    int e = v.x >> 1, role = v.x & 1;
    int other = v.y;
    const float* qb = &g_Q[(size_t)e * 32 + (role ? 0 : 16)];
    const float* hb = &g_H[(size_t)other * 256 + cl * 4];

    #pragma unroll
    for (int jj = 0; jj < 2; jj++) {
        int j = g + jj * 2;
        float4 qv = *(const float4*)&qb[j * 4];
        float4 hv = *(const float4*)&hb[j * 64];
        part[0][0] += qv.x * hv.x; part[0][1] += qv.x * hv.y;
        part[0][2] += qv.x * hv.z; part[0][3] += qv.x * hv.w;
        part[1][0] += qv.y * hv.x; part[1][1] += qv.y * hv.y;
        part[1][2] += qv.y * hv.z; part[1][3] += qv.y * hv.w;
        part[2][0] += qv.z * hv.x; part[2][1] += qv.z * hv.y;
        part[2][2] += qv.z * hv.z; part[2][3] += qv.z * hv.w;
        part[3][0] += qv.w * hv.x; part[3][1] += qv.w * hv.y;
        part[3][2] += qv.w * hv.z; part[3][3] += qv.w * hv.w;
    }
}

__global__ __launch_bounds__(256)
void gather_kernel()
{
    __shared__ float red[4][32][16];
    int warp = threadIdx.x >> 5, lane = threadIdx.x & 31;
    int slot = warp >> 1, w2 = warp & 1;
    int n = blockIdx.x * 4 + slot;     // grid 5000, exact
    int beg = g_off[n], endi = g_off[n + 1];
    int cnt = endi - beg;
    int mid = beg + ((cnt + 1) >> 1);
    int lo = w2 ? mid : beg;
    int hi = w2 ? endi : mid;
    int g = lane >> 4, cl = lane & 15;

    float part[4][4] = {};

    int idx = lo;
    for (; idx + 1 < hi; idx += 2) {
        proc_inc2(idx,     g, cl, part);
        proc_inc2(idx + 1, g, cl, part);
    }
    if (idx < hi) proc_inc2(idx, g, cl, part);

    if (w2) {
        #pragma unroll
        for (int i = 0; i < 4; i++)
            #pragma unroll
            for (int c = 0; c < 4; c++)
                red[slot][lane][i * 4 + c] = part[i][c];
    }
    __syncthreads();
    if (!w2) {
        #pragma unroll
        for (int i = 0; i < 4; i++)
            #pragma unroll
            for (int c = 0; c < 4; c++)
                part[i][c] += red[slot][lane][i * 4 + c];

        const float* db = &g_zs.D[n * 16];
        const float* hb = &g_H[(size_t)n * 256 + cl * 4];
        float lh[4][4];
        {
            float4 qv0 = *(const float4*)&db[g * 4];
            float4 hv0 = *(const float4*)&hb[g * 64];
            float4 qv1 = *(const float4*)&db[(g + 2) * 4];
            float4 hv1 = *(const float4*)&hb[(g + 2) * 64];
            #pragma unroll
            for (int i = 0; i < 4; i++) {
                float qi0 = (i == 0 ? qv0.x : i == 1 ? qv0.y : i == 2 ? qv0.z : qv0.w);
                float qi1 = (i == 0 ? qv1.x : i == 1 ? qv1.y : i == 2 ? qv1.z : qv1.w);
                lh[i][0] = qi0 * hv0.x + qi1 * hv1.x - part[i][0];
                lh[i][1] = qi0 * hv0.y + qi1 * hv1.y - part[i][1];
                lh[i][2] = qi0 * hv0.z + qi1 * hv1.z - part[i][2];
                lh[i][3] = qi0 * hv0.w + qi1 * hv1.w - part[i][3];
            }
        }
        #pragma unroll
        for (int i = 0; i < 4; i++)
            #pragma unroll
            for (int c = 0; c < 4; c++)
                lh[i][c] += __shfl_xor_sync(0xffffffffu, lh[i][c], 16);

        #pragma unroll
        for (int r = 0; r < 2; r++) {
            int i = g * 2 + r;
            float* xp = &g_h[(size_t)n * 256 + i * 64 + cl * 4];
            float4 xv = *(const float4*)xp;
            xv.x -= fmaxf(lh[i][0], 0.f);
            xv.y -= fmaxf(lh[i][1], 0.f);
            xv.z -= fmaxf(lh[i][2], 0.f);
            xv.w -= fmaxf(lh[i][3], 0.f);
            *(float4*)xp = xv;
        }
    }
}

// ---------------- launch (stream-forked DAG) ----------------
static cudaStream_t s_s1, s_s2;
static cudaEvent_t  s_evRoot, s_evG1b, s_evWc, s_evMs, s_evComb, s_evHc0, s_evFill;
static bool s_init = false;

extern "C" void kernel_launch(void* const* d_in, const int* in_sizes, int n_in,
                              void* d_out, int out_size)
{
    const float* x    = (const float*)d_in[0];
    const int*   ei   = (const int*)  d_in[1];
    const float* Win1 = (const float*)d_in[2];
    const float* bin1 = (const float*)d_in[3];
    const float* Win2 = (const float*)d_in[4];
    const float* bin2 = (const float*)d_in[5];
    const float* Wm1  = (const float*)d_in[6];
    const float* bm1  = (const float*)d_in[7];
    const float* Wm2  = (const float*)d_in[8];
    const float* bm2  = (const float*)d_in[9];
    const float* Wd1  = (const float*)d_in[10];
    const float* Wd2  = (const float*)d_in[11];
    const float* Wo1  = (const float*)d_in[12];
    const float* bo1  = (const float*)d_in[13];
    const float* Wo2  = (const float*)d_in[14];
    const float* bo2  = (const float*)d_in[15];
    float* out = (float*)d_out;

    if (!s_init) {   // host-side resources only; device work identical per call
        cudaStreamCreateWithFlags(&s_s1, cudaStreamNonBlocking);
        cudaStreamCreateWithFlags(&s_s2, cudaStreamNonBlocking);
        cudaEventCreateWithFlags(&s_evRoot, cudaEventDisableTiming);
        cudaEventCreateWithFlags(&s_evG1b,  cudaEventDisableTiming);
        cudaEventCreateWithFlags(&s_evWc,   cudaEventDisableTiming);
        cudaEventCreateWithFlags(&s_evMs,   cudaEventDisableTiming);
        cudaEventCreateWithFlags(&s_evComb, cudaEventDisableTiming);
        cudaEventCreateWithFlags(&s_evHc0,  cudaEventDisableTiming);
        cudaEventCreateWithFlags(&s_evFill, cudaEventDisableTiming);
        s_init = true;
    }

    void *p_zs, *p_h, *p_h1, *p_p0, *p_p1, *p_AB, *p_Wc, *p_bc;
    cudaGetSymbolAddress(&p_zs, g_zs);
    cudaGetSymbolAddress(&p_h,  g_h);
    cudaGetSymbolAddress(&p_h1, g_h1);
    cudaGetSymbolAddress(&p_p0, g_p0);
    cudaGetSymbolAddress(&p_p1, g_p1);
    cudaGetSymbolAddress(&p_AB, g_AB);
    cudaGetSymbolAddress(&p_Wc, g_Wc);
    cudaGetSymbolAddress(&p_bc, g_bc);
    float* h   = (float*)p_h;
    float* h1  = (float*)p_h1;
    float* P0  = (float*)p_p0;
    float* P1  = (float*)p_p1;
    float* AB  = (float*)p_AB;
    float* Wc  = (float*)p_Wc;
    float* bc  = (float*)p_bc;

    const int MB = (N_NODES + 127) / 128;  // 157

    // ---- fork side streams off the capture-origin stream (0) ----
    cudaEventRecord(s_evRoot, 0);
    cudaStreamWaitEvent(s_s1, s_evRoot, 0);
    cudaStreamWaitEvent(s_s2, s_evRoot, 0);

    // ---- s2: weights-combine + CSR chain (independent of node features) ----
    wc_kernel<<<128, 256, 0, s_s2>>>(Wm1, Win2, bin2);
    cudaEventRecord(s_evWc, s_s2);
    cudaMemsetAsync(p_zs, 0, sizeof(ZS), s_s2);
    cudaEventRecord(s_evMs, s_s2);
    count_kernel<<<(N_EDGES + 255) / 256, 256, 0, s_s2>>>(ei);
    scan_kernel<<<1, 1024, 0, s_s2>>>();
    fill_kernel<<<(N_EDGES + 255) / 256, 256, 0, s_s2>>>(ei);
    cudaEventRecord(s_evFill, s_s2);

    // ---- s1: second split-K half of input MLP ----
    sgemm128<false><<<dim3(1, MB), 256, 0, s_s1>>>(x + 256, Win1 + 256, nullptr, P1,
                                                   N_NODES, 64, 244, IN_DIM, IN_DIM);
    cudaEventRecord(s_evG1b, s_s1);

    // ---- stream 0: critical path to edge ----
    sgemm128<false><<<dim3(1, MB), 256>>>(x, Win1, nullptr, P0,
                                          N_NODES, 64, 256, IN_DIM, IN_DIM);
    cudaStreamWaitEvent(0, s_evG1b, 0);
    combine_kernel<<<(N_NODES * 64 / 4 + 255) / 256, 256>>>(bin1);
    cudaEventRecord(s_evComb, 0);
    cudaStreamWaitEvent(0, s_evWc, 0);
    sgemm128<false><<<dim3(2, MB), 256>>>(h1, Wc, bc, AB, N_NODES, 128, 64, 64, 64);
    cudaStreamWaitEvent(0, s_evMs, 0);
    edge_kernel<<<N_EDGES / 8, 256>>>(ei, Wm2, bm1, bm2);

    // ---- s1 (parallel with AB/edge): h = h1@Win2^T + bin2; hcomp layer 0 ----
    cudaStreamWaitEvent(s_s1, s_evComb, 0);
    sgemm128<false><<<dim3(4, MB), 256, 0, s_s1>>>(h1, Win2, bin2, h,
                                                   N_NODES, 256, 64, 64, 64);
    hcomp_kernel<<<N_NODES / 8, 256, 0, s_s1>>>(Wd1, Wd2, 0);
    cudaEventRecord(s_evHc0, s_s1);

    // ---- join: gather layer 0 needs edge(0) + fill(s2) + hcomp0(s1) ----
    cudaStreamWaitEvent(0, s_evFill, 0);
    cudaStreamWaitEvent(0, s_evHc0, 0);
    gather_kernel<<<N_NODES / 4, 256>>>();
    hcomp_kernel<<<N_NODES / 8, 256>>>(Wd1, Wd2, 1);
    gather_kernel<<<N_NODES / 4, 256>>>();

    // ---- output MLP ----
    sgemm128<true ><<<dim3(1, MB), 256>>>(h,  Wo1, bo1, h1,  N_NODES, 64, 256, 256, 256);
    sgemm128<false><<<dim3(1, MB), 256>>>(h1, Wo2, bo2, out, N_NODES, 16, 64, 64, 64);
}

// round 9
// speedup vs baseline: 1.2978x; 1.0298x over previous
#include <cuda_runtime.h>
#include <cuda_bf16.h>

#define N_NODES 20000
#define N_EDGES 200000
#define IN_DIM  500
#define HID     256
#define OUT_DIM 16
#define MHD     64

// ---------------- device scratch (static, no allocations) ----------------
struct ZS {                     // zeroed by ONE memset each launch
    int   cnt[N_NODES];
    float D[N_NODES * 16];      // per-node sum of P (src) + S (dst); symmetric
};
__device__ ZS    g_zs;
__device__ float g_h  [N_NODES * HID];     // h, then xb (updated in place)
__device__ float g_h1 [N_NODES * MHD];     // MLP intermediates
__device__ float g_p0 [N_NODES * MHD];     // split-K partials for input MLP
__device__ float g_p1 [N_NODES * MHD];
__device__ float g_AB [N_NODES * 2 * MHD]; // [N][128]: A | B
__device__ float g_Wc [2 * MHD * MHD];     // combined (Wab @ Win2) -> [128][64]
__device__ float g_bc [2 * MHD];           // combined bias Wab @ bin2
__device__ float g_Q  [(size_t)N_EDGES * 32]; // per edge: Q row-major, Q^T row-major
__device__ float g_H  [N_NODES * HID];     // diffusion operand H per layer
__device__ int   g_off[N_NODES + 1];
__device__ int   g_cur[N_NODES];
__device__ int2  g_incid[2 * N_EDGES];     // {(e<<1)|role, other}

// ---------------- SGEMM: C = act(A[M,K](lda) @ W[N,K](ldw)^T + b) --------
template<bool RELU>
__global__ __launch_bounds__(256, 2)
void sgemm128(const float* __restrict__ A, const float* __restrict__ W,
              const float* __restrict__ bias, float* __restrict__ C,
              int M, int N, int K, int lda, int ldw)
{
    __shared__ float As[16][132];
    __shared__ float Ws[16][68];

    int tid = threadIdx.x;
    int tx = tid & 15, ty = tid >> 4;
    int row0 = blockIdx.y * 128, col0 = blockIdx.x * 64;

    int arow = tid >> 1;
    int akb  = (tid & 1) * 8;
    int wcol = tid & 63;
    int wkb  = (tid >> 6) * 4;

    int gr = row0 + arow;
    int gc = col0 + wcol;
    const float* Arow = A + (size_t)(gr < M ? gr : 0) * lda;
    const float* Wrow = W + (size_t)(gc < N ? gc : 0) * ldw;
    bool rok = gr < M;
    bool cok = gc < N;

    float acc[8][4] = {};
    float ra[8], rw[4];

    #pragma unroll
    for (int u = 0; u < 8; u++) {
        int k = akb + u;
        ra[u] = (rok && k < K) ? Arow[k] : 0.f;
    }
    #pragma unroll
    for (int u = 0; u < 4; u++) {
        int k = wkb + u;
        rw[u] = (cok && k < K) ? Wrow[k] : 0.f;
    }

    for (int k0 = 0; k0 < K; k0 += 16) {
        #pragma unroll
        for (int u = 0; u < 8; u++) As[akb + u][arow] = ra[u];
        #pragma unroll
        for (int u = 0; u < 4; u++) Ws[wkb + u][wcol] = rw[u];
        __syncthreads();

        int kn = k0 + 16;
        if (kn < K) {
            #pragma unroll
            for (int u = 0; u < 8; u++) {
                int k = kn + akb + u;
                ra[u] = (rok && k < K) ? Arow[k] : 0.f;
            }
            #pragma unroll
            for (int u = 0; u < 4; u++) {
                int k = kn + wkb + u;
                rw[u] = (cok && k < K) ? Wrow[k] : 0.f;
            }
        }

        #pragma unroll
        for (int kk = 0; kk < 16; kk++) {
            float4 a0 = *(const float4*)&As[kk][ty * 8];
            float4 a1 = *(const float4*)&As[kk][ty * 8 + 4];
            float4 b0 = *(const float4*)&Ws[kk][tx * 4];
            float a[8] = {a0.x, a0.y, a0.z, a0.w, a1.x, a1.y, a1.z, a1.w};
            float b[4] = {b0.x, b0.y, b0.z, b0.w};
            #pragma unroll
            for (int i = 0; i < 8; i++)
                #pragma unroll
                for (int j = 0; j < 4; j++)
                    acc[i][j] += a[i] * b[j];
        }
        __syncthreads();
    }

    #pragma unroll
    for (int i = 0; i < 8; i++) {
        int r = row0 + ty * 8 + i;
        if (r >= M) continue;
        #pragma unroll
        for (int j = 0; j < 4; j++) {
            int c = col0 + tx * 4 + j;
            if (c >= N) continue;
            float v = acc[i][j] + (bias ? bias[c] : 0.f);
            if (RELU) v = fmaxf(v, 0.f);
            C[(size_t)r * N + c] = v;
        }
    }
}

// ---------------- fused output MLP: out = relu(xb@Wo1^T+bo1)@Wo2^T+bo2 ---
// Phase 1 == sgemm128 (M=20000, N=64, K=256) but tile lands in smem.
__global__ __launch_bounds__(256, 2)
void outmlp_kernel(const float* __restrict__ A,  const float* __restrict__ W1,
                   const float* __restrict__ b1v, const float* __restrict__ W2,
                   const float* __restrict__ b2v, float* __restrict__ C)
{
    __shared__ float buf[128 * 68];   // phase1: As(16x132)+Ws(16x68); phase2: h1s[128][68]
    __shared__ float W2t[64 * 16];    // Wo2 transposed: W2t[k][c]
    float (*As)[132] = (float(*)[132])buf;
    float (*Ws)[68]  = (float(*)[68])(buf + 16 * 132);

    const int M = N_NODES, K = 256;
    int tid = threadIdx.x;
    for (int i = tid; i < 1024; i += 256)          // W2 is [16][64] row-major
        W2t[(i & 63) * 16 + (i >> 6)] = W2[i];

    int tx = tid & 15, ty = tid >> 4;
    int row0 = blockIdx.x * 128;
    int arow = tid >> 1;
    int akb  = (tid & 1) * 8;
    int wcol = tid & 63;
    int wkb  = (tid >> 6) * 4;

    int gr = row0 + arow;
    const float* Arow = A + (size_t)(gr < M ? gr : 0) * 256;
    const float* Wrow = W1 + (size_t)wcol * 256;
    bool rok = gr < M;

    float acc[8][4] = {};
    float ra[8], rw[4];
    #pragma unroll
    for (int u = 0; u < 8; u++) ra[u] = rok ? Arow[akb + u] : 0.f;
    #pragma unroll
    for (int u = 0; u < 4; u++) rw[u] = Wrow[wkb + u];

    for (int k0 = 0; k0 < K; k0 += 16) {
        #pragma unroll
        for (int u = 0; u < 8; u++) As[akb + u][arow] = ra[u];
        #pragma unroll
        for (int u = 0; u < 4; u++) Ws[wkb + u][wcol] = rw[u];
        __syncthreads();

        int kn = k0 + 16;
        if (kn < K) {
            #pragma unroll
            for (int u = 0; u < 8; u++) ra[u] = rok ? Arow[kn + akb + u] : 0.f;
            #pragma unroll
            for (int u = 0; u < 4; u++) rw[u] = Wrow[kn + wkb + u];
        }

        #pragma unroll
        for (int kk = 0; kk < 16; kk++) {
            float4 a0 = *(const float4*)&As[kk][ty * 8];
            float4 a1 = *(const float4*)&As[kk][ty * 8 + 4];
            float4 b0 = *(const float4*)&Ws[kk][tx * 4];
            float a[8] = {a0.x, a0.y, a0.z, a0.w, a1.x, a1.y, a1.z, a1.w};
            float b[4] = {b0.x, b0.y, b0.z, b0.w};
            #pragma unroll
            for (int i = 0; i < 8; i++)
                #pragma unroll
                for (int j = 0; j < 4; j++)
                    acc[i][j] += a[i] * b[j];
        }
        __syncthreads();
    }

    // write relu(h1) tile into smem (reuses As/Ws region; all reads done)
    float* h1s = buf;
    #pragma unroll
    for (int i = 0; i < 8; i++) {
        int r = ty * 8 + i;
        #pragma unroll
        for (int j = 0; j < 4; j++) {
            int c = tx * 4 + j;
            h1s[r * 68 + c] = fmaxf(acc[i][j] + b1v[c], 0.f);
        }
    }
    __syncthreads();

    // phase 2: 2 threads per row, 8 output cols each
    int row = tid >> 1, ch = tid & 1;
    float a8[8] = {};
    #pragma unroll 8
    for (int k = 0; k < 64; k++) {
        float hv = h1s[row * 68 + k];
        float4 wA = *(const float4*)&W2t[k * 16 + ch * 8];
        float4 wB = *(const float4*)&W2t[k * 16 + ch * 8 + 4];
        a8[0] += hv * wA.x; a8[1] += hv * wA.y;
        a8[2] += hv * wA.z; a8[3] += hv * wA.w;
        a8[4] += hv * wB.x; a8[5] += hv * wB.y;
        a8[6] += hv * wB.z; a8[7] += hv * wB.w;
    }
    int gr2 = row0 + row;
    if (gr2 < M) {
        float4 bA = *(const float4*)&b2v[ch * 8];
        float4 bB = *(const float4*)&b2v[ch * 8 + 4];
        float4 oA = make_float4(a8[0] + bA.x, a8[1] + bA.y, a8[2] + bA.z, a8[3] + bA.w);
        float4 oB = make_float4(a8[4] + bB.x, a8[5] + bB.y, a8[6] + bB.z, a8[7] + bB.w);
        *(float4*)&C[(size_t)gr2 * 16 + ch * 8]     = oA;
        *(float4*)&C[(size_t)gr2 * 16 + ch * 8 + 4] = oB;
    }
}

// ---------------- combine split-K partials: h1 = relu(p0+p1+bias) --------
__global__ __launch_bounds__(256)
void combine_kernel(const float* __restrict__ bias)
{
    int i = blockIdx.x * 256 + threadIdx.x;    // float4 index, < 320000
    float4 a = ((const float4*)g_p0)[i];
    float4 b = ((const float4*)g_p1)[i];
    float4 bs = *(const float4*)&bias[(i * 4) & 63];
    float4 r;
    r.x = fmaxf(a.x + b.x + bs.x, 0.f);
    r.y = fmaxf(a.y + b.y + bs.y, 0.f);
    r.z = fmaxf(a.z + b.z + bs.z, 0.f);
    r.w = fmaxf(a.w + b.w + bs.w, 0.f);
    ((float4*)g_h1)[i] = r;
}

// ---------------- CSR build ----------------
__global__ void count_kernel(const int* __restrict__ ei) {
    int e = blockIdx.x * 256 + threadIdx.x;
    if (e < N_EDGES) {
        atomicAdd(&g_zs.cnt[ei[e]], 1);
        atomicAdd(&g_zs.cnt[ei[N_EDGES + e]], 1);
    }
}

__global__ void scan_kernel() {
    const int CH = (N_NODES + 1023) / 1024;  // 20
    __shared__ int ssum[1024];
    int tid = threadIdx.x;
    int begin = tid * CH;
    int endi = begin + CH; if (endi > N_NODES) endi = N_NODES;
    int s = 0;
    for (int i = begin; i < endi; i++) s += g_zs.cnt[i];
    ssum[tid] = s;
    __syncthreads();
    for (int off = 1; off < 1024; off <<= 1) {
        int v = 0;
        if (tid >= off) v = ssum[tid - off];
        __syncthreads();
        ssum[tid] += v;
        __syncthreads();
    }
    int run = ssum[tid] - s;
    for (int i = begin; i < endi; i++) {
        g_off[i] = run;
        g_cur[i] = run;
        run += g_zs.cnt[i];
    }
    if (tid == 1023) g_off[N_NODES] = ssum[1023];
}

__global__ void fill_kernel(const int* __restrict__ ei) {
    int e = blockIdx.x * 256 + threadIdx.x;
    if (e < N_EDGES) {
        int s = ei[e], d = ei[N_EDGES + e];
        int p = atomicAdd(&g_cur[s], 1);
        g_incid[p] = make_int2(e << 1, d);         // node is src, other = dst
        int p2 = atomicAdd(&g_cur[d], 1);
        g_incid[p2] = make_int2((e << 1) | 1, s);  // node is dst, other = src
    }
}

// ---------------- combined weights: Wc = Wab @ Win2, bc = Wab @ bin2 -----
__global__ __launch_bounds__(256)
void wc_kernel(const float* __restrict__ Wm1,
               const float* __restrict__ Win2,
               const float* __restrict__ bin2)
{
    __shared__ float part[256];
    __shared__ float bpart[64];
    int i = blockIdx.x;                  // 0..127
    const float* wrow = (i < 64) ? &Wm1[i * 512] : &Wm1[(i - 64) * 512 + 256];
    int t = threadIdx.x;
    int mh = t & 63, kq = t >> 6;
    float s = 0.f;
    #pragma unroll 16
    for (int k = kq * 64; k < kq * 64 + 64; k++)
        s += wrow[k] * Win2[k * 64 + mh];
    part[t] = s;
    if (kq == 0) {
        float b = 0.f;
        #pragma unroll
        for (int k = mh * 4; k < mh * 4 + 4; k++) b += wrow[k] * bin2[k];
        bpart[mh] = b;
    }
    __syncthreads();
    if (kq == 0)
        g_Wc[i * 64 + mh] = part[mh] + part[64 + mh] + part[128 + mh] + part[192 + mh];
    if (t == 0) {
        float bb = 0.f;
        #pragma unroll
        for (int k = 0; k < 64; k++) bb += bpart[k];
        g_bc[i] = bb;
    }
}

// ---------------- per-edge: Q & Q^T; P,S atomics into D ------------------
__global__ __launch_bounds__(256)
void edge_kernel(const int* __restrict__ ei, const float* __restrict__ Wm2,
                 const float* __restrict__ bm1, const float* __restrict__ bm2)
{
    __shared__ float W4s[1024];      // Wm2 repacked: [(k>>2)][o][k&3]
    __shared__ float bm2s[16];
    __shared__ float sbuf[8 * 160];  // per warp: t1[64] t2[64] fsft[32]
    int tid = threadIdx.x;
    for (int idx = tid; idx < 1024; idx += 256) {
        int o = idx >> 6, k = idx & 63;
        W4s[((k >> 2) << 6) + (o << 2) + (k & 3)] = Wm2[idx];
    }
    if (tid < 16) bm2s[tid] = bm2[tid];
    __syncthreads();

    int warp = tid >> 5, lane = tid & 31;
    int e = blockIdx.x * 8 + warp;   // grid 25000, exact
    float* sw = &sbuf[warp * 160];

    int s = ei[e], d = ei[N_EDGES + e];
    int k0 = lane * 2;
    float2 As = *(const float2*)&g_AB[s * 128 + k0];
    float2 Bd = *(const float2*)&g_AB[d * 128 + 64 + k0];
    float2 Ad = *(const float2*)&g_AB[d * 128 + k0];
    float2 Bs = *(const float2*)&g_AB[s * 128 + 64 + k0];
    float2 b1 = *(const float2*)&bm1[k0];
    float2 t1v = make_float2(fmaxf(As.x + Bd.x + b1.x, 0.f),
                             fmaxf(As.y + Bd.y + b1.y, 0.f));
    float2 t2v = make_float2(fmaxf(Ad.x + Bs.x + b1.x, 0.f),
                             fmaxf(Ad.y + Bs.y + b1.y, 0.f));
    *(float2*)&sw[k0]      = t1v;
    *(float2*)&sw[64 + k0] = t2v;
    __syncwarp();

    // lanes 0-15 -> fs[o] from t1; lanes 16-31 -> ft[o] from t2
    int o = lane & 15;
    const float* tv = sw + ((lane >> 4) << 6);
    float accf = 0.f;
    #pragma unroll
    for (int kc = 0; kc < 16; kc++) {
        float4 t = *(const float4*)&tv[kc * 4];
        float4 w = *(const float4*)&W4s[kc * 64 + o * 4];
        accf += t.x * w.x + t.y * w.y + t.z * w.z + t.w * w.w;
    }
    accf += bm2s[o];
    sw[128 + lane] = accf;
    __syncwarp();

    if (lane < 16) {
        int i = lane >> 2, j = lane & 3;
        float p = 0.f, q = 0.f, ss = 0.f;
        #pragma unroll
        for (int m = 0; m < 4; m++) {
            float fsi = sw[128 + m * 4 + i], fsj = sw[128 + m * 4 + j];
            float fti = sw[144 + m * 4 + i], ftj = sw[144 + m * 4 + j];
            p  += fsi * fsj;   // P = Fs^T Fs  (symmetric)
            q  += fsi * ftj;   // Q = Fs^T Ft
            ss += fti * ftj;   // S = Ft^T Ft  (symmetric)
        }
        float* qb = &g_Q[(size_t)e * 32];
        qb[lane] = q;                          // Q  row-major [i][j]
        qb[16 + j * 4 + i] = q;                // Q^T row-major [j][i]
        atomicAdd(&g_zs.D[s * 16 + lane], p);
        atomicAdd(&g_zs.D[d * 16 + lane], ss);
    }
}

// ---------------- per-node H = (Wd1^T @ xb) @ Wd2^T ----------------------
__global__ __launch_bounds__(256)
void hcomp_kernel(const float* __restrict__ Wd1, const float* __restrict__ Wd2,
                  int layer)
{
    __shared__ float w2s[64 * 65];   // w2s[g*65 + f] = Wd2[l][g][f]
    __shared__ float h1s[8][4][64];
    int tid = threadIdx.x;
    for (int idx = tid; idx < 4096; idx += 256) {
        int g = idx >> 6, f = idx & 63;
        w2s[g * 65 + f] = Wd2[layer * 4096 + idx];
    }
    float wd1[16];
    #pragma unroll
    for (int i = 0; i < 16; i++) wd1[i] = __ldg(&Wd1[layer * 16 + i]);

    int warp = tid >> 5, lane = tid & 31;
    int n = blockIdx.x * 8 + warp;   // grid 2500, exact
    int c0 = lane * 2;
    float2 xv[4];
    #pragma unroll
    for (int j = 0; j < 4; j++)
        xv[j] = *(const float2*)&g_h[n * 256 + j * 64 + c0];
    #pragma unroll
    for (int i = 0; i < 4; i++) {
        h1s[warp][i][c0]     = wd1[i] * xv[0].x + wd1[4 + i] * xv[1].x +
                               wd1[8 + i] * xv[2].x + wd1[12 + i] * xv[3].x;
        h1s[warp][i][c0 + 1] = wd1[i] * xv[0].y + wd1[4 + i] * xv[1].y +
                               wd1[8 + i] * xv[2].y + wd1[12 + i] * xv[3].y;
    }
    __syncthreads();

    int ca = lane, cb = lane + 32;
    float acca[4] = {0, 0, 0, 0};
    float accb[4] = {0, 0, 0, 0};
    #pragma unroll
    for (int f0 = 0; f0 < 64; f0 += 4) {
        float4 h0 = *(const float4*)&h1s[warp][0][f0];
        float4 h1 = *(const float4*)&h1s[warp][1][f0];
        float4 h2 = *(const float4*)&h1s[warp][2][f0];
        float4 h3 = *(const float4*)&h1s[warp][3][f0];
        const float* wa = &w2s[ca * 65 + f0];
        const float* wb = &w2s[cb * 65 + f0];
        float wa0 = wa[0], wa1 = wa[1], wa2 = wa[2], wa3 = wa[3];
        float wb0 = wb[0], wb1 = wb[1], wb2 = wb[2], wb3 = wb[3];
        acca[0] += h0.x * wa0 + h0.y * wa1 + h0.z * wa2 + h0.w * wa3;
        acca[1] += h1.x * wa0 + h1.y * wa1 + h1.z * wa2 + h1.w * wa3;
        acca[2] += h2.x * wa0 + h2.y * wa1 + h2.z * wa2 + h2.w * wa3;
        acca[3] += h3.x * wa0 + h3.y * wa1 + h3.z * wa2 + h3.w * wa3;
        accb[0] += h0.x * wb0 + h0.y * wb1 + h0.z * wb2 + h0.w * wb3;
        accb[1] += h1.x * wb0 + h1.y * wb1 + h1.z * wb2 + h1.w * wb3;
        accb[2] += h2.x * wb0 + h2.y * wb1 + h2.z * wb2 + h2.w * wb3;
        accb[3] += h3.x * wb0 + h3.y * wb1 + h3.z * wb2 + h3.w * wb3;
    }
    #pragma unroll
    for (int k = 0; k < 4; k++) {
        g_H[n * 256 + k * 64 + ca] = acca[k];
        g_H[n * 256 + k * 64 + cb] = accb[k];
    }
}

// ---------------- gather: 5 LDG per incidence, deferred butterfly --------
__device__ __forceinline__ void proc_inc2(int idx, int g, int cl, float part[4][4])
{
    int2 v = __ldg(&g_incid[idx]);
    int e = v.x >> 1, role = v.x & 1;
    int other = v.y;
    const float* qb = &g_Q[(size_t)e * 32 + (role ? 0 : 16)];
    const float* hb = &g_H[(size_t)other * 256 + cl * 4];

    #pragma unroll
    for (int jj = 0; jj < 2; jj++) {
        int j = g + jj * 2;
        float4 qv = *(const float4*)&qb[j * 4];
        float4 hv = *(const float4*)&hb[j * 64];
        part[0][0] += qv.x * hv.x; part[0][1] += qv.x * hv.y;
        part[0][2] += qv.x * hv.z; part[0][3] += qv.x * hv.w;
        part[1][0] += qv.y * hv.x; part[1][1] += qv.y * hv.y;
        part[1][2] += qv.y * hv.z; part[1][3] += qv.y * hv.w;
        part[2][0] += qv.z * hv.x; part[2][1] += qv.z * hv.y;
        part[2][2] += qv.z * hv.z; part[2][3] += qv.z * hv.w;
        part[3][0] += qv.w * hv.x; part[3][1] += qv.w * hv.y;
        part[3][2] += qv.w * hv.z; part[3][3] += qv.w * hv.w;
    }
}

__global__ __launch_bounds__(256)
void gather_kernel()
{
    __shared__ float red[4][32][16];
    int warp = threadIdx.x >> 5, lane = threadIdx.x & 31;
    int slot = warp >> 1, w2 = warp & 1;
    int n = blockIdx.x * 4 + slot;     // grid 5000, exact
    int beg = g_off[n], endi = g_off[n + 1];
    int cnt = endi - beg;
    int mid = beg + ((cnt + 1) >> 1);
    int lo = w2 ? mid : beg;
    int hi = w2 ? endi : mid;
    int g = lane >> 4, cl = lane & 15;

    float part[4][4] = {};

    int idx = lo;
    for (; idx + 1 < hi; idx += 2) {
        proc_inc2(idx,     g, cl, part);
        proc_inc2(idx + 1, g, cl, part);
    }
    if (idx < hi) proc_inc2(idx, g, cl, part);

    if (w2) {
        #pragma unroll
        for (int i = 0; i < 4; i++)
            #pragma unroll
            for (int c = 0; c < 4; c++)
                red[slot][lane][i * 4 + c] = part[i][c];
    }
    __syncthreads();
    if (!w2) {
        #pragma unroll
        for (int i = 0; i < 4; i++)
            #pragma unroll
            for (int c = 0; c < 4; c++)
                part[i][c] += red[slot][lane][i * 4 + c];

        const float* db = &g_zs.D[n * 16];
        const float* hb = &g_H[(size_t)n * 256 + cl * 4];
        float lh[4][4];
        {
            float4 qv0 = *(const float4*)&db[g * 4];
            float4 hv0 = *(const float4*)&hb[g * 64];
            float4 qv1 = *(const float4*)&db[(g + 2) * 4];
            float4 hv1 = *(const float4*)&hb[(g + 2) * 64];
            #pragma unroll
            for (int i = 0; i < 4; i++) {
                float qi0 = (i == 0 ? qv0.x : i == 1 ? qv0.y : i == 2 ? qv0.z : qv0.w);
                float qi1 = (i == 0 ? qv1.x : i == 1 ? qv1.y : i == 2 ? qv1.z : qv1.w);
                lh[i][0] = qi0 * hv0.x + qi1 * hv1.x - part[i][0];
                lh[i][1] = qi0 * hv0.y + qi1 * hv1.y - part[i][1];
                lh[i][2] = qi0 * hv0.z + qi1 * hv1.z - part[i][2];
                lh[i][3] = qi0 * hv0.w + qi1 * hv1.w - part[i][3];
            }
        }
        #pragma unroll
        for (int i = 0; i < 4; i++)
            #pragma unroll
            for (int c = 0; c < 4; c++)
                lh[i][c] += __shfl_xor_sync(0xffffffffu, lh[i][c], 16);

        #pragma unroll
        for (int r = 0; r < 2; r++) {
            int i = g * 2 + r;
            float* xp = &g_h[(size_t)n * 256 + i * 64 + cl * 4];
            float4 xv = *(const float4*)xp;
            xv.x -= fmaxf(lh[i][0], 0.f);
            xv.y -= fmaxf(lh[i][1], 0.f);
            xv.z -= fmaxf(lh[i][2], 0.f);
            xv.w -= fmaxf(lh[i][3], 0.f);
            *(float4*)xp = xv;
        }
    }
}

// ---------------- launch (stream-forked DAG) ----------------
static cudaStream_t s_s1, s_s2;
static cudaEvent_t  s_evRoot, s_evG1b, s_evWc, s_evMs, s_evComb, s_evHc0, s_evFill;
static bool s_init = false;

extern "C" void kernel_launch(void* const* d_in, const int* in_sizes, int n_in,
                              void* d_out, int out_size)
{
    const float* x    = (const float*)d_in[0];
    const int*   ei   = (const int*)  d_in[1];
    const float* Win1 = (const float*)d_in[2];
    const float* bin1 = (const float*)d_in[3];
    const float* Win2 = (const float*)d_in[4];
    const float* bin2 = (const float*)d_in[5];
    const float* Wm1  = (const float*)d_in[6];
    const float* bm1  = (const float*)d_in[7];
    const float* Wm2  = (const float*)d_in[8];
    const float* bm2  = (const float*)d_in[9];
    const float* Wd1  = (const float*)d_in[10];
    const float* Wd2  = (const float*)d_in[11];
    const float* Wo1  = (const float*)d_in[12];
    const float* bo1  = (const float*)d_in[13];
    const float* Wo2  = (const float*)d_in[14];
    const float* bo2  = (const float*)d_in[15];
    float* out = (float*)d_out;

    if (!s_init) {   // host-side resources only; device work identical per call
        cudaStreamCreateWithFlags(&s_s1, cudaStreamNonBlocking);
        cudaStreamCreateWithFlags(&s_s2, cudaStreamNonBlocking);
        cudaEventCreateWithFlags(&s_evRoot, cudaEventDisableTiming);
        cudaEventCreateWithFlags(&s_evG1b,  cudaEventDisableTiming);
        cudaEventCreateWithFlags(&s_evWc,   cudaEventDisableTiming);
        cudaEventCreateWithFlags(&s_evMs,   cudaEventDisableTiming);
        cudaEventCreateWithFlags(&s_evComb, cudaEventDisableTiming);
        cudaEventCreateWithFlags(&s_evHc0,  cudaEventDisableTiming);
        cudaEventCreateWithFlags(&s_evFill, cudaEventDisableTiming);
        s_init = true;
    }

    void *p_zs, *p_h, *p_h1, *p_p0, *p_p1, *p_AB, *p_Wc, *p_bc;
    cudaGetSymbolAddress(&p_zs, g_zs);
    cudaGetSymbolAddress(&p_h,  g_h);
    cudaGetSymbolAddress(&p_h1, g_h1);
    cudaGetSymbolAddress(&p_p0, g_p0);
    cudaGetSymbolAddress(&p_p1, g_p1);
    cudaGetSymbolAddress(&p_AB, g_AB);
    cudaGetSymbolAddress(&p_Wc, g_Wc);
    cudaGetSymbolAddress(&p_bc, g_bc);
    float* h   = (float*)p_h;
    float* h1  = (float*)p_h1;
    float* P0  = (float*)p_p0;
    float* P1  = (float*)p_p1;
    float* AB  = (float*)p_AB;
    float* Wc  = (float*)p_Wc;
    float* bc  = (float*)p_bc;

    const int MB = (N_NODES + 127) / 128;  // 157

    // ---- fork side streams off the capture-origin stream (0) ----
    cudaEventRecord(s_evRoot, 0);
    cudaStreamWaitEvent(s_s1, s_evRoot, 0);
    cudaStreamWaitEvent(s_s2, s_evRoot, 0);

    // ---- s2: weights-combine + CSR chain (independent of node features) ----
    wc_kernel<<<128, 256, 0, s_s2>>>(Wm1, Win2, bin2);
    cudaEventRecord(s_evWc, s_s2);
    cudaMemsetAsync(p_zs, 0, sizeof(ZS), s_s2);
    cudaEventRecord(s_evMs, s_s2);
    count_kernel<<<(N_EDGES + 255) / 256, 256, 0, s_s2>>>(ei);
    scan_kernel<<<1, 1024, 0, s_s2>>>();
    fill_kernel<<<(N_EDGES + 255) / 256, 256, 0, s_s2>>>(ei);
    cudaEventRecord(s_evFill, s_s2);

    // ---- s1: second split-K half of input MLP ----
    sgemm128<false><<<dim3(1, MB), 256, 0, s_s1>>>(x + 256, Win1 + 256, nullptr, P1,
                                                   N_NODES, 64, 244, IN_DIM, IN_DIM);
    cudaEventRecord(s_evG1b, s_s1);

    // ---- stream 0: critical path to edge ----
    sgemm128<false><<<dim3(1, MB), 256>>>(x, Win1, nullptr, P0,
                                          N_NODES, 64, 256, IN_DIM, IN_DIM);
    cudaStreamWaitEvent(0, s_evG1b, 0);
    combine_kernel<<<(N_NODES * 64 / 4 + 255) / 256, 256>>>(bin1);
    cudaEventRecord(s_evComb, 0);
    cudaStreamWaitEvent(0, s_evWc, 0);
    sgemm128<false><<<dim3(2, MB), 256>>>(h1, Wc, bc, AB, N_NODES, 128, 64, 64, 64);
    cudaStreamWaitEvent(0, s_evMs, 0);
    edge_kernel<<<N_EDGES / 8, 256>>>(ei, Wm2, bm1, bm2);

    // ---- s1 (parallel with AB/edge): h = h1@Win2^T + bin2; hcomp layer 0 ----
    cudaStreamWaitEvent(s_s1, s_evComb, 0);
    sgemm128<false><<<dim3(4, MB), 256, 0, s_s1>>>(h1, Win2, bin2, h,
                                                   N_NODES, 256, 64, 64, 64);
    hcomp_kernel<<<N_NODES / 8, 256, 0, s_s1>>>(Wd1, Wd2, 0);
    cudaEventRecord(s_evHc0, s_s1);

    // ---- join: gather layer 0 needs edge(0) + fill(s2) + hcomp0(s1) ----
    cudaStreamWaitEvent(0, s_evFill, 0);
    cudaStreamWaitEvent(0, s_evHc0, 0);
    gather_kernel<<<N_NODES / 4, 256>>>();
    hcomp_kernel<<<N_NODES / 8, 256>>>(Wd1, Wd2, 1);
    gather_kernel<<<N_NODES / 4, 256>>>();

    // ---- fused output MLP ----
    outmlp_kernel<<<MB, 256>>>(h, Wo1, bo1, Wo2, bo2, out);
}

// round 10
// speedup vs baseline: 1.4515x; 1.1184x over previous
#include <cuda_runtime.h>
#include <cuda_bf16.h>

#define N_NODES 20000
#define N_EDGES 200000
#define IN_DIM  500
#define HID     256
#define OUT_DIM 16
#define MHD     64

// ---------------- device scratch (static, no allocations) ----------------
struct ZS {                     // zeroed by ONE memset each launch
    int   cnt[N_NODES];
    float D[N_NODES * 16];      // per-node sum of P (src) + S (dst); symmetric
};
__device__ ZS    g_zs;
__device__ float g_h  [N_NODES * HID];     // h, then xb (updated in place)
__device__ float g_h1 [N_NODES * MHD];     // MLP intermediates
__device__ float g_p0 [N_NODES * MHD];     // split-K partials for input MLP
__device__ float g_p1 [N_NODES * MHD];
__device__ float g_AB [N_NODES * 2 * MHD]; // [N][128]: A | B
__device__ float g_Wc [2 * MHD * MHD];     // combined (Wab @ Win2) -> [128][64]
__device__ float g_bc [2 * MHD];           // combined bias Wab @ bin2
__device__ float g_Q  [(size_t)N_EDGES * 32]; // per edge: Q row-major, Q^T row-major
__device__ float g_H  [N_NODES * HID];     // diffusion operand H per layer
__device__ int   g_off[N_NODES + 1];
__device__ int   g_cur[N_NODES];
__device__ int2  g_incid[2 * N_EDGES];     // {(e<<1)|role, other}

// ---------------- SGEMM: C = act(A[M,K](lda) @ W[N,K](ldw)^T + b) --------
template<bool RELU>
__global__ __launch_bounds__(256, 2)
void sgemm128(const float* __restrict__ A, const float* __restrict__ W,
              const float* __restrict__ bias, float* __restrict__ C,
              int M, int N, int K, int lda, int ldw)
{
    __shared__ float As[16][132];
    __shared__ float Ws[16][68];

    int tid = threadIdx.x;
    int tx = tid & 15, ty = tid >> 4;
    int row0 = blockIdx.y * 128, col0 = blockIdx.x * 64;

    int arow = tid >> 1;
    int akb  = (tid & 1) * 8;
    int wcol = tid & 63;
    int wkb  = (tid >> 6) * 4;

    int gr = row0 + arow;
    int gc = col0 + wcol;
    const float* Arow = A + (size_t)(gr < M ? gr : 0) * lda;
    const float* Wrow = W + (size_t)(gc < N ? gc : 0) * ldw;
    bool rok = gr < M;
    bool cok = gc < N;

    float acc[8][4] = {};
    float ra[8], rw[4];

    #pragma unroll
    for (int u = 0; u < 8; u++) {
        int k = akb + u;
        ra[u] = (rok && k < K) ? Arow[k] : 0.f;
    }
    #pragma unroll
    for (int u = 0; u < 4; u++) {
        int k = wkb + u;
        rw[u] = (cok && k < K) ? Wrow[k] : 0.f;
    }

    for (int k0 = 0; k0 < K; k0 += 16) {
        #pragma unroll
        for (int u = 0; u < 8; u++) As[akb + u][arow] = ra[u];
        #pragma unroll
        for (int u = 0; u < 4; u++) Ws[wkb + u][wcol] = rw[u];
        __syncthreads();

        int kn = k0 + 16;
        if (kn < K) {
            #pragma unroll
            for (int u = 0; u < 8; u++) {
                int k = kn + akb + u;
                ra[u] = (rok && k < K) ? Arow[k] : 0.f;
            }
            #pragma unroll
            for (int u = 0; u < 4; u++) {
                int k = kn + wkb + u;
                rw[u] = (cok && k < K) ? Wrow[k] : 0.f;
            }
        }

        #pragma unroll
        for (int kk = 0; kk < 16; kk++) {
            float4 a0 = *(const float4*)&As[kk][ty * 8];
            float4 a1 = *(const float4*)&As[kk][ty * 8 + 4];
            float4 b0 = *(const float4*)&Ws[kk][tx * 4];
            float a[8] = {a0.x, a0.y, a0.z, a0.w, a1.x, a1.y, a1.z, a1.w};
            float b[4] = {b0.x, b0.y, b0.z, b0.w};
            #pragma unroll
            for (int i = 0; i < 8; i++)
                #pragma unroll
                for (int j = 0; j < 4; j++)
                    acc[i][j] += a[i] * b[j];
        }
        __syncthreads();
    }

    #pragma unroll
    for (int i = 0; i < 8; i++) {
        int r = row0 + ty * 8 + i;
        if (r >= M) continue;
        #pragma unroll
        for (int j = 0; j < 4; j++) {
            int c = col0 + tx * 4 + j;
            if (c >= N) continue;
            float v = acc[i][j] + (bias ? bias[c] : 0.f);
            if (RELU) v = fmaxf(v, 0.f);
            C[(size_t)r * N + c] = v;
        }
    }
}

// ---------------- fused output MLP: out = relu(xb@Wo1^T+bo1)@Wo2^T+bo2 ---
__global__ __launch_bounds__(256, 2)
void outmlp_kernel(const float* __restrict__ A,  const float* __restrict__ W1,
                   const float* __restrict__ b1v, const float* __restrict__ W2,
                   const float* __restrict__ b2v, float* __restrict__ C)
{
    __shared__ float buf[128 * 68];   // phase1: As(16x132)+Ws(16x68); phase2: h1s[128][68]
    __shared__ float W2t[64 * 16];    // Wo2 transposed: W2t[k][c]
    float (*As)[132] = (float(*)[132])buf;
    float (*Ws)[68]  = (float(*)[68])(buf + 16 * 132);

    const int M = N_NODES, K = 256;
    int tid = threadIdx.x;
    for (int i = tid; i < 1024; i += 256)          // W2 is [16][64] row-major
        W2t[(i & 63) * 16 + (i >> 6)] = W2[i];

    int tx = tid & 15, ty = tid >> 4;
    int row0 = blockIdx.x * 128;
    int arow = tid >> 1;
    int akb  = (tid & 1) * 8;
    int wcol = tid & 63;
    int wkb  = (tid >> 6) * 4;

    int gr = row0 + arow;
    const float* Arow = A + (size_t)(gr < M ? gr : 0) * 256;
    const float* Wrow = W1 + (size_t)wcol * 256;
    bool rok = gr < M;

    float acc[8][4] = {};
    float ra[8], rw[4];
    #pragma unroll
    for (int u = 0; u < 8; u++) ra[u] = rok ? Arow[akb + u] : 0.f;
    #pragma unroll
    for (int u = 0; u < 4; u++) rw[u] = Wrow[wkb + u];

    for (int k0 = 0; k0 < K; k0 += 16) {
        #pragma unroll
        for (int u = 0; u < 8; u++) As[akb + u][arow] = ra[u];
        #pragma unroll
        for (int u = 0; u < 4; u++) Ws[wkb + u][wcol] = rw[u];
        __syncthreads();

        int kn = k0 + 16;
        if (kn < K) {
            #pragma unroll
            for (int u = 0; u < 8; u++) ra[u] = rok ? Arow[kn + akb + u] : 0.f;
            #pragma unroll
            for (int u = 0; u < 4; u++) rw[u] = Wrow[kn + wkb + u];
        }

        #pragma unroll
        for (int kk = 0; kk < 16; kk++) {
            float4 a0 = *(const float4*)&As[kk][ty * 8];
            float4 a1 = *(const float4*)&As[kk][ty * 8 + 4];
            float4 b0 = *(const float4*)&Ws[kk][tx * 4];
            float a[8] = {a0.x, a0.y, a0.z, a0.w, a1.x, a1.y, a1.z, a1.w};
            float b[4] = {b0.x, b0.y, b0.z, b0.w};
            #pragma unroll
            for (int i = 0; i < 8; i++)
                #pragma unroll
                for (int j = 0; j < 4; j++)
                    acc[i][j] += a[i] * b[j];
        }
        __syncthreads();
    }

    // write relu(h1) tile into smem (reuses As/Ws region; all reads done)
    float* h1s = buf;
    #pragma unroll
    for (int i = 0; i < 8; i++) {
        int r = ty * 8 + i;
        #pragma unroll
        for (int j = 0; j < 4; j++) {
            int c = tx * 4 + j;
            h1s[r * 68 + c] = fmaxf(acc[i][j] + b1v[c], 0.f);
        }
    }
    __syncthreads();

    // phase 2: 2 threads per row, 8 output cols each
    int row = tid >> 1, ch = tid & 1;
    float a8[8] = {};
    #pragma unroll 8
    for (int k = 0; k < 64; k++) {
        float hv = h1s[row * 68 + k];
        float4 wA = *(const float4*)&W2t[k * 16 + ch * 8];
        float4 wB = *(const float4*)&W2t[k * 16 + ch * 8 + 4];
        a8[0] += hv * wA.x; a8[1] += hv * wA.y;
        a8[2] += hv * wA.z; a8[3] += hv * wA.w;
        a8[4] += hv * wB.x; a8[5] += hv * wB.y;
        a8[6] += hv * wB.z; a8[7] += hv * wB.w;
    }
    int gr2 = row0 + row;
    if (gr2 < M) {
        float4 bA = *(const float4*)&b2v[ch * 8];
        float4 bB = *(const float4*)&b2v[ch * 8 + 4];
        float4 oA = make_float4(a8[0] + bA.x, a8[1] + bA.y, a8[2] + bA.z, a8[3] + bA.w);
        float4 oB = make_float4(a8[4] + bB.x, a8[5] + bB.y, a8[6] + bB.z, a8[7] + bB.w);
        *(float4*)&C[(size_t)gr2 * 16 + ch * 8]     = oA;
        *(float4*)&C[(size_t)gr2 * 16 + ch * 8 + 4] = oB;
    }
}

// ---------------- combine split-K partials: h1 = relu(p0+p1+bias) --------
__global__ __launch_bounds__(256)
void combine_kernel(const float* __restrict__ bias)
{
    int i = blockIdx.x * 256 + threadIdx.x;    // float4 index, < 320000
    float4 a = ((const float4*)g_p0)[i];
    float4 b = ((const float4*)g_p1)[i];
    float4 bs = *(const float4*)&bias[(i * 4) & 63];
    float4 r;
    r.x = fmaxf(a.x + b.x + bs.x, 0.f);
    r.y = fmaxf(a.y + b.y + bs.y, 0.f);
    r.z = fmaxf(a.z + b.z + bs.z, 0.f);
    r.w = fmaxf(a.w + b.w + bs.w, 0.f);
    ((float4*)g_h1)[i] = r;
}

// ---------------- CSR build ----------------
__global__ void count_kernel(const int* __restrict__ ei) {
    int e = blockIdx.x * 256 + threadIdx.x;
    if (e < N_EDGES) {
        atomicAdd(&g_zs.cnt[ei[e]], 1);
        atomicAdd(&g_zs.cnt[ei[N_EDGES + e]], 1);
    }
}

__global__ void scan_kernel() {
    const int CH = (N_NODES + 1023) / 1024;  // 20
    __shared__ int ssum[1024];
    int tid = threadIdx.x;
    int begin = tid * CH;
    int endi = begin + CH; if (endi > N_NODES) endi = N_NODES;
    int s = 0;
    for (int i = begin; i < endi; i++) s += g_zs.cnt[i];
    ssum[tid] = s;
    __syncthreads();
    for (int off = 1; off < 1024; off <<= 1) {
        int v = 0;
        if (tid >= off) v = ssum[tid - off];
        __syncthreads();
        ssum[tid] += v;
        __syncthreads();
    }
    int run = ssum[tid] - s;
    for (int i = begin; i < endi; i++) {
        g_off[i] = run;
        g_cur[i] = run;
        run += g_zs.cnt[i];
    }
    if (tid == 1023) g_off[N_NODES] = ssum[1023];
}

__global__ void fill_kernel(const int* __restrict__ ei) {
    int e = blockIdx.x * 256 + threadIdx.x;
    if (e < N_EDGES) {
        int s = ei[e], d = ei[N_EDGES + e];
        int p = atomicAdd(&g_cur[s], 1);
        g_incid[p] = make_int2(e << 1, d);         // node is src, other = dst
        int p2 = atomicAdd(&g_cur[d], 1);
        g_incid[p2] = make_int2((e << 1) | 1, s);  // node is dst, other = src
    }
}

// ---------------- combined weights: Wc = Wab @ Win2, bc = Wab @ bin2 -----
__global__ __launch_bounds__(256)
void wc_kernel(const float* __restrict__ Wm1,
               const float* __restrict__ Win2,
               const float* __restrict__ bin2)
{
    __shared__ float part[256];
    __shared__ float bpart[64];
    int i = blockIdx.x;                  // 0..127
    const float* wrow = (i < 64) ? &Wm1[i * 512] : &Wm1[(i - 64) * 512 + 256];
    int t = threadIdx.x;
    int mh = t & 63, kq = t >> 6;
    float s = 0.f;
    #pragma unroll 16
    for (int k = kq * 64; k < kq * 64 + 64; k++)
        s += wrow[k] * Win2[k * 64 + mh];
    part[t] = s;
    if (kq == 0) {
        float b = 0.f;
        #pragma unroll
        for (int k = mh * 4; k < mh * 4 + 4; k++) b += wrow[k] * bin2[k];
        bpart[mh] = b;
    }
    __syncthreads();
    if (kq == 0)
        g_Wc[i * 64 + mh] = part[mh] + part[64 + mh] + part[128 + mh] + part[192 + mh];
    if (t == 0) {
        float bb = 0.f;
        #pragma unroll
        for (int k = 0; k < 64; k++) bb += bpart[k];
        g_bc[i] = bb;
    }
}

// ---------------- per-edge v3: weights-in-regs, 8 edges/warp, shfl fsft --
__global__ __launch_bounds__(256, 2)
void edge_kernel(const int* __restrict__ ei, const float* __restrict__ Wm2,
                 const float* __restrict__ bm1, const float* __restrict__ bm2)
{
    __shared__ float W4s[1024];      // Wm2 repacked: [(k>>2)][o][k&3]
    __shared__ float sbuf[8 * 128];  // per warp: t1[64] t2[64]
    int tid = threadIdx.x;
    for (int idx = tid; idx < 1024; idx += 256) {
        int o = idx >> 6, k = idx & 63;
        W4s[((k >> 2) << 6) + (o << 2) + (k & 3)] = Wm2[idx];
    }
    __syncthreads();

    int warp = tid >> 5, lane = tid & 31;
    int o = lane & 15;
    float* sw = &sbuf[warp * 128];
    int k0 = lane * 2;

    // per-lane invariants: Wm2 row o in registers, biases
    float4 wreg[16];
    #pragma unroll
    for (int kc = 0; kc < 16; kc++)
        wreg[kc] = *(const float4*)&W4s[kc * 64 + o * 4];
    float2 b1 = *(const float2*)&bm1[k0];
    float bm2o = __ldg(&bm2[o]);
    int i = o >> 2, j = o & 3;

    int e0 = (blockIdx.x * 8 + warp) * 8;   // grid 3125, exact: 8 edges per warp

    // prefetch edge 0
    int sA = ei[e0], dA = ei[N_EDGES + e0];
    float2 AsA = *(const float2*)&g_AB[sA * 128 + k0];
    float2 BdA = *(const float2*)&g_AB[dA * 128 + 64 + k0];
    float2 AdA = *(const float2*)&g_AB[dA * 128 + k0];
    float2 BsA = *(const float2*)&g_AB[sA * 128 + 64 + k0];

    #pragma unroll
    for (int t = 0; t < 8; t++) {
        int e = e0 + t;
        // prefetch edge t+1 (independent chain, hides L2 latency)
        int sB = 0, dB = 0;
        float2 AsB, BdB, AdB, BsB;
        if (t < 7) {
            sB = ei[e + 1]; dB = ei[N_EDGES + e + 1];
            AsB = *(const float2*)&g_AB[sB * 128 + k0];
            BdB = *(const float2*)&g_AB[dB * 128 + 64 + k0];
            AdB = *(const float2*)&g_AB[dB * 128 + k0];
            BsB = *(const float2*)&g_AB[sB * 128 + 64 + k0];
        }

        float2 t1v = make_float2(fmaxf(AsA.x + BdA.x + b1.x, 0.f),
                                 fmaxf(AsA.y + BdA.y + b1.y, 0.f));
        float2 t2v = make_float2(fmaxf(AdA.x + BsA.x + b1.x, 0.f),
                                 fmaxf(AdA.y + BsA.y + b1.y, 0.f));
        __syncwarp();            // prior iteration's LDS complete before overwrite
        *(float2*)&sw[k0]      = t1v;
        *(float2*)&sw[64 + k0] = t2v;
        __syncwarp();

        // lanes 0-15 -> fs[o] from t1; 16-31 -> ft[o] from t2 (weights in regs)
        const float* tv = sw + ((lane >> 4) << 6);
        float accf = 0.f;
        #pragma unroll
        for (int kc = 0; kc < 16; kc++) {
            float4 tval = *(const float4*)&tv[kc * 4];
            float4 w = wreg[kc];
            accf += tval.x * w.x + tval.y * w.y + tval.z * w.z + tval.w * w.w;
        }
        accf += bm2o;

        // P,Q,S via shuffles (no smem round-trip); all lanes participate
        float p = 0.f, q = 0.f, ss = 0.f;
        #pragma unroll
        for (int m = 0; m < 4; m++) {
            float fsi = __shfl_sync(0xffffffffu, accf, m * 4 + i);
            float fsj = __shfl_sync(0xffffffffu, accf, m * 4 + j);
            float fti = __shfl_sync(0xffffffffu, accf, 16 + m * 4 + i);
            float ftj = __shfl_sync(0xffffffffu, accf, 16 + m * 4 + j);
            p  += fsi * fsj;   // P = Fs^T Fs  (symmetric)
            q  += fsi * ftj;   // Q = Fs^T Ft
            ss += fti * ftj;   // S = Ft^T Ft  (symmetric)
        }
        if (lane < 16) {
            float* qb = &g_Q[(size_t)e * 32];
            qb[lane] = q;                          // Q  row-major [i][j]
            qb[16 + j * 4 + i] = q;                // Q^T row-major [j][i]
            atomicAdd(&g_zs.D[sA * 16 + lane], p);
            atomicAdd(&g_zs.D[dA * 16 + lane], ss);
        }

        sA = sB; dA = dB;
        AsA = AsB; BdA = BdB; AdA = AdB; BsA = BsB;
    }
}

// ---------------- per-node H = (Wd1^T @ xb) @ Wd2^T ----------------------
__global__ __launch_bounds__(256)
void hcomp_kernel(const float* __restrict__ Wd1, const float* __restrict__ Wd2,
                  int layer)
{
    __shared__ float w2s[64 * 65];   // w2s[g*65 + f] = Wd2[l][g][f]
    __shared__ float h1s[8][4][64];
    int tid = threadIdx.x;
    for (int idx = tid; idx < 4096; idx += 256) {
        int g = idx >> 6, f = idx & 63;
        w2s[g * 65 + f] = Wd2[layer * 4096 + idx];
    }
    float wd1[16];
    #pragma unroll
    for (int i = 0; i < 16; i++) wd1[i] = __ldg(&Wd1[layer * 16 + i]);

    int warp = tid >> 5, lane = tid & 31;
    int n = blockIdx.x * 8 + warp;   // grid 2500, exact
    int c0 = lane * 2;
    float2 xv[4];
    #pragma unroll
    for (int j = 0; j < 4; j++)
        xv[j] = *(const float2*)&g_h[n * 256 + j * 64 + c0];
    #pragma unroll
    for (int i = 0; i < 4; i++) {
        h1s[warp][i][c0]     = wd1[i] * xv[0].x + wd1[4 + i] * xv[1].x +
                               wd1[8 + i] * xv[2].x + wd1[12 + i] * xv[3].x;
        h1s[warp][i][c0 + 1] = wd1[i] * xv[0].y + wd1[4 + i] * xv[1].y +
                               wd1[8 + i] * xv[2].y + wd1[12 + i] * xv[3].y;
    }
    __syncthreads();

    int ca = lane, cb = lane + 32;
    float acca[4] = {0, 0, 0, 0};
    float accb[4] = {0, 0, 0, 0};
    #pragma unroll
    for (int f0 = 0; f0 < 64; f0 += 4) {
        float4 h0 = *(const float4*)&h1s[warp][0][f0];
        float4 h1 = *(const float4*)&h1s[warp][1][f0];
        float4 h2 = *(const float4*)&h1s[warp][2][f0];
        float4 h3 = *(const float4*)&h1s[warp][3][f0];
        const float* wa = &w2s[ca * 65 + f0];
        const float* wb = &w2s[cb * 65 + f0];
        float wa0 = wa[0], wa1 = wa[1], wa2 = wa[2], wa3 = wa[3];
        float wb0 = wb[0], wb1 = wb[1], wb2 = wb[2], wb3 = wb[3];
        acca[0] += h0.x * wa0 + h0.y * wa1 + h0.z * wa2 + h0.w * wa3;
        acca[1] += h1.x * wa0 + h1.y * wa1 + h1.z * wa2 + h1.w * wa3;
        acca[2] += h2.x * wa0 + h2.y * wa1 + h2.z * wa2 + h2.w * wa3;
        acca[3] += h3.x * wa0 + h3.y * wa1 + h3.z * wa2 + h3.w * wa3;
        accb[0] += h0.x * wb0 + h0.y * wb1 + h0.z * wb2 + h0.w * wb3;
        accb[1] += h1.x * wb0 + h1.y * wb1 + h1.z * wb2 + h1.w * wb3;
        accb[2] += h2.x * wb0 + h2.y * wb1 + h2.z * wb2 + h2.w * wb3;
        accb[3] += h3.x * wb0 + h3.y * wb1 + h3.z * wb2 + h3.w * wb3;
    }
    #pragma unroll
    for (int k = 0; k < 4; k++) {
        g_H[n * 256 + k * 64 + ca] = acca[k];
        g_H[n * 256 + k * 64 + cb] = accb[k];
    }
}

// ---------------- gather: 5 LDG per incidence, deferred butterfly --------
__device__ __forceinline__ void proc_inc2(int idx, int g, int cl, float part[4][4])
{
    int2 v = __ldg(&g_incid[idx]);
    int e = v.x >> 1, role = v.x & 1;
    int other = v.y;
    const float* qb = &g_Q[(size_t)e * 32 + (role ? 0 : 16)];
    const float* hb = &g_H[(size_t)other * 256 + cl * 4];

    #pragma unroll
    for (int jj = 0; jj < 2; jj++) {
        int j = g + jj * 2;
        float4 qv = *(const float4*)&qb[j * 4];
        float4 hv = *(const float4*)&hb[j * 64];
        part[0][0] += qv.x * hv.x; part[0][1] += qv.x * hv.y;
        part[0][2] += qv.x * hv.z; part[0][3] += qv.x * hv.w;
        part[1][0] += qv.y * hv.x; part[1][1] += qv.y * hv.y;
        part[1][2] += qv.y * hv.z; part[1][3] += qv.y * hv.w;
        part[2][0] += qv.z * hv.x; part[2][1] += qv.z * hv.y;
        part[2][2] += qv.z * hv.z; part[2][3] += qv.z * hv.w;
        part[3][0] += qv.w * hv.x; part[3][1] += qv.w * hv.y;
        part[3][2] += qv.w * hv.z; part[3][3] += qv.w * hv.w;
    }
}

__global__ __launch_bounds__(256)
void gather_kernel()
{
    __shared__ float red[4][32][16];
    int warp = threadIdx.x >> 5, lane = threadIdx.x & 31;
    int slot = warp >> 1, w2 = warp & 1;
    int n = blockIdx.x * 4 + slot;     // grid 5000, exact
    int beg = g_off[n], endi = g_off[n + 1];
    int cnt = endi - beg;
    int mid = beg + ((cnt + 1) >> 1);
    int lo = w2 ? mid : beg;
    int hi = w2 ? endi : mid;
    int g = lane >> 4, cl = lane & 15;

    float part[4][4] = {};

    int idx = lo;
    for (; idx + 1 < hi; idx += 2) {
        proc_inc2(idx,     g, cl, part);
        proc_inc2(idx + 1, g, cl, part);
    }
    if (idx < hi) proc_inc2(idx, g, cl, part);

    if (w2) {
        #pragma unroll
        for (int i = 0; i < 4; i++)
            #pragma unroll
            for (int c = 0; c < 4; c++)
                red[slot][lane][i * 4 + c] = part[i][c];
    }
    __syncthreads();
    if (!w2) {
        #pragma unroll
        for (int i = 0; i < 4; i++)
            #pragma unroll
            for (int c = 0; c < 4; c++)
                part[i][c] += red[slot][lane][i * 4 + c];

        const float* db = &g_zs.D[n * 16];
        const float* hb = &g_H[(size_t)n * 256 + cl * 4];
        float lh[4][4];
        {
            float4 qv0 = *(const float4*)&db[g * 4];
            float4 hv0 = *(const float4*)&hb[g * 64];
            float4 qv1 = *(const float4*)&db[(g + 2) * 4];
            float4 hv1 = *(const float4*)&hb[(g + 2) * 64];
            #pragma unroll
            for (int i = 0; i < 4; i++) {
                float qi0 = (i == 0 ? qv0.x : i == 1 ? qv0.y : i == 2 ? qv0.z : qv0.w);
                float qi1 = (i == 0 ? qv1.x : i == 1 ? qv1.y : i == 2 ? qv1.z : qv1.w);
                lh[i][0] = qi0 * hv0.x + qi1 * hv1.x - part[i][0];
                lh[i][1] = qi0 * hv0.y + qi1 * hv1.y - part[i][1];
                lh[i][2] = qi0 * hv0.z + qi1 * hv1.z - part[i][2];
                lh[i][3] = qi0 * hv0.w + qi1 * hv1.w - part[i][3];
            }
        }
        #pragma unroll
        for (int i = 0; i < 4; i++)
            #pragma unroll
            for (int c = 0; c < 4; c++)
                lh[i][c] += __shfl_xor_sync(0xffffffffu, lh[i][c], 16);

        #pragma unroll
        for (int r = 0; r < 2; r++) {
            int i = g * 2 + r;
            float* xp = &g_h[(size_t)n * 256 + i * 64 + cl * 4];
            float4 xv = *(const float4*)xp;
            xv.x -= fmaxf(lh[i][0], 0.f);
            xv.y -= fmaxf(lh[i][1], 0.f);
            xv.z -= fmaxf(lh[i][2], 0.f);
            xv.w -= fmaxf(lh[i][3], 0.f);
            *(float4*)xp = xv;
        }
    }
}

// ---------------- launch (stream-forked DAG) ----------------
static cudaStream_t s_s1, s_s2;
static cudaEvent_t  s_evRoot, s_evG1b, s_evWc, s_evMs, s_evComb, s_evHc0, s_evFill;
static bool s_init = false;

extern "C" void kernel_launch(void* const* d_in, const int* in_sizes, int n_in,
                              void* d_out, int out_size)
{
    const float* x    = (const float*)d_in[0];
    const int*   ei   = (const int*)  d_in[1];
    const float* Win1 = (const float*)d_in[2];
    const float* bin1 = (const float*)d_in[3];
    const float* Win2 = (const float*)d_in[4];
    const float* bin2 = (const float*)d_in[5];
    const float* Wm1  = (const float*)d_in[6];
    const float* bm1  = (const float*)d_in[7];
    const float* Wm2  = (const float*)d_in[8];
    const float* bm2  = (const float*)d_in[9];
    const float* Wd1  = (const float*)d_in[10];
    const float* Wd2  = (const float*)d_in[11];
    const float* Wo1  = (const float*)d_in[12];
    const float* bo1  = (const float*)d_in[13];
    const float* Wo2  = (const float*)d_in[14];
    const float* bo2  = (const float*)d_in[15];
    float* out = (float*)d_out;

    if (!s_init) {   // host-side resources only; device work identical per call
        cudaStreamCreateWithFlags(&s_s1, cudaStreamNonBlocking);
        cudaStreamCreateWithFlags(&s_s2, cudaStreamNonBlocking);
        cudaEventCreateWithFlags(&s_evRoot, cudaEventDisableTiming);
        cudaEventCreateWithFlags(&s_evG1b,  cudaEventDisableTiming);
        cudaEventCreateWithFlags(&s_evWc,   cudaEventDisableTiming);
        cudaEventCreateWithFlags(&s_evMs,   cudaEventDisableTiming);
        cudaEventCreateWithFlags(&s_evComb, cudaEventDisableTiming);
        cudaEventCreateWithFlags(&s_evHc0,  cudaEventDisableTiming);
        cudaEventCreateWithFlags(&s_evFill, cudaEventDisableTiming);
        s_init = true;
    }

    void *p_zs, *p_h, *p_h1, *p_p0, *p_p1, *p_AB, *p_Wc, *p_bc;
    cudaGetSymbolAddress(&p_zs, g_zs);
    cudaGetSymbolAddress(&p_h,  g_h);
    cudaGetSymbolAddress(&p_h1, g_h1);
    cudaGetSymbolAddress(&p_p0, g_p0);
    cudaGetSymbolAddress(&p_p1, g_p1);
    cudaGetSymbolAddress(&p_AB, g_AB);
    cudaGetSymbolAddress(&p_Wc, g_Wc);
    cudaGetSymbolAddress(&p_bc, g_bc);
    float* h   = (float*)p_h;
    float* h1  = (float*)p_h1;
    float* P0  = (float*)p_p0;
    float* P1  = (float*)p_p1;
    float* AB  = (float*)p_AB;
    float* Wc  = (float*)p_Wc;
    float* bc  = (float*)p_bc;

    const int MB = (N_NODES + 127) / 128;  // 157

    // ---- fork side streams off the capture-origin stream (0) ----
    cudaEventRecord(s_evRoot, 0);
    cudaStreamWaitEvent(s_s1, s_evRoot, 0);
    cudaStreamWaitEvent(s_s2, s_evRoot, 0);

    // ---- s2: weights-combine + CSR chain (independent of node features) ----
    wc_kernel<<<128, 256, 0, s_s2>>>(Wm1, Win2, bin2);
    cudaEventRecord(s_evWc, s_s2);
    cudaMemsetAsync(p_zs, 0, sizeof(ZS), s_s2);
    cudaEventRecord(s_evMs, s_s2);
    count_kernel<<<(N_EDGES + 255) / 256, 256, 0, s_s2>>>(ei);
    scan_kernel<<<1, 1024, 0, s_s2>>>();
    fill_kernel<<<(N_EDGES + 255) / 256, 256, 0, s_s2>>>(ei);
    cudaEventRecord(s_evFill, s_s2);

    // ---- s1: second split-K half of input MLP ----
    sgemm128<false><<<dim3(1, MB), 256, 0, s_s1>>>(x + 256, Win1 + 256, nullptr, P1,
                                                   N_NODES, 64, 244, IN_DIM, IN_DIM);
    cudaEventRecord(s_evG1b, s_s1);

    // ---- stream 0: critical path to edge ----
    sgemm128<false><<<dim3(1, MB), 256>>>(x, Win1, nullptr, P0,
                                          N_NODES, 64, 256, IN_DIM, IN_DIM);
    cudaStreamWaitEvent(0, s_evG1b, 0);
    combine_kernel<<<(N_NODES * 64 / 4 + 255) / 256, 256>>>(bin1);
    cudaEventRecord(s_evComb, 0);
    cudaStreamWaitEvent(0, s_evWc, 0);
    sgemm128<false><<<dim3(2, MB), 256>>>(h1, Wc, bc, AB, N_NODES, 128, 64, 64, 64);
    cudaStreamWaitEvent(0, s_evMs, 0);
    edge_kernel<<<N_EDGES / 64, 256>>>(ei, Wm2, bm1, bm2);

    // ---- s1 (parallel with AB/edge): h = h1@Win2^T + bin2; hcomp layer 0 ----
    cudaStreamWaitEvent(s_s1, s_evComb, 0);
    sgemm128<false><<<dim3(4, MB), 256, 0, s_s1>>>(h1, Win2, bin2, h,
                                                   N_NODES, 256, 64, 64, 64);
    hcomp_kernel<<<N_NODES / 8, 256, 0, s_s1>>>(Wd1, Wd2, 0);
    cudaEventRecord(s_evHc0, s_s1);

    // ---- join: gather layer 0 needs edge(0) + fill(s2) + hcomp0(s1) ----
    cudaStreamWaitEvent(0, s_evFill, 0);
    cudaStreamWaitEvent(0, s_evHc0, 0);
    gather_kernel<<<N_NODES / 4, 256>>>();
    hcomp_kernel<<<N_NODES / 8, 256>>>(Wd1, Wd2, 1);
    gather_kernel<<<N_NODES / 4, 256>>>();

    // ---- fused output MLP ----
    outmlp_kernel<<<MB, 256>>>(h, Wo1, bo1, Wo2, bo2, out);
}